// round 3
// baseline (speedup 1.0000x reference)
#include <cuda_runtime.h>
#include <math.h>

#define BATCH   16
#define CDIM    512
#define HW      4096
#define MQKV    1536
#define NHEADS  8
#define DHEAD   64
#define LN_EPS  1e-5f

// Scratch (device globals — no cudaMalloc allowed)
__device__ float g_qkv[(size_t)BATCH * MQKV * HW];   // ~402 MB
__device__ float g_att[(size_t)BATCH * CDIM * HW];   // ~134 MB
__device__ float g_psum[BATCH * 64];
__device__ float g_psq [BATCH * 64];
__device__ float g_stats[BATCH * 2];

// ---------------------------------------------------------------------------
// GEMM: Y[b][m][n] = sum_k W[m][k] * X[b][k][n] (+ bias[m])
// BM=BN=128, BK=16, 256 threads, 8x8 micro-tile per thread.
// grid = (HW/128, M/128, BATCH)
// ---------------------------------------------------------------------------
__global__ __launch_bounds__(256)
void gemm_wx(const float* __restrict__ W, const float* __restrict__ X,
             float* __restrict__ Y, const float* __restrict__ bias, int K)
{
    __shared__ float As[16][128];   // [k][m]
    __shared__ float Bs[16][128];   // [k][n]

    const int b  = blockIdx.z;
    const int m0 = blockIdx.y * 128;
    const int n0 = blockIdx.x * 128;
    const int tid = threadIdx.x;

    const float* Wp = W + (size_t)m0 * K;
    const float* Xp = X + (size_t)b * K * HW + n0;

    float acc[8][8];
#pragma unroll
    for (int i = 0; i < 8; i++)
#pragma unroll
        for (int j = 0; j < 8; j++) acc[i][j] = 0.0f;

    const int ar = tid >> 2;            // 0..63
    const int ac = (tid & 3) * 4;       // 0,4,8,12
    const int br = tid >> 5;            // 0..7
    const int bc = (tid & 31) * 4;      // 0..124
    const int tm = (tid >> 4) * 8;      // 0..120
    const int tn = (tid & 15) * 8;      // 0..120

    for (int k0 = 0; k0 < K; k0 += 16) {
        float4 a0 = *(const float4*)(Wp + (size_t)ar        * K + k0 + ac);
        float4 a1 = *(const float4*)(Wp + (size_t)(ar + 64) * K + k0 + ac);
        float4 x0 = *(const float4*)(Xp + (size_t)(k0 + br)     * HW + bc);
        float4 x1 = *(const float4*)(Xp + (size_t)(k0 + br + 8) * HW + bc);

        __syncthreads();
        As[ac + 0][ar]      = a0.x; As[ac + 1][ar]      = a0.y;
        As[ac + 2][ar]      = a0.z; As[ac + 3][ar]      = a0.w;
        As[ac + 0][ar + 64] = a1.x; As[ac + 1][ar + 64] = a1.y;
        As[ac + 2][ar + 64] = a1.z; As[ac + 3][ar + 64] = a1.w;
        *(float4*)(&Bs[br][bc])     = x0;
        *(float4*)(&Bs[br + 8][bc]) = x1;
        __syncthreads();

#pragma unroll
        for (int kk = 0; kk < 16; kk++) {
            float av[8], bv[8];
            *(float4*)(av)     = *(const float4*)(&As[kk][tm]);
            *(float4*)(av + 4) = *(const float4*)(&As[kk][tm + 4]);
            *(float4*)(bv)     = *(const float4*)(&Bs[kk][tn]);
            *(float4*)(bv + 4) = *(const float4*)(&Bs[kk][tn + 4]);
#pragma unroll
            for (int i = 0; i < 8; i++)
#pragma unroll
                for (int j = 0; j < 8; j++)
                    acc[i][j] = fmaf(av[i], bv[j], acc[i][j]);
        }
    }

    const int M = gridDim.y * 128;
    float* Yp = Y + (size_t)b * M * HW;
    float bb[8];
#pragma unroll
    for (int i = 0; i < 8; i++) bb[i] = bias ? bias[m0 + tm + i] : 0.0f;

#pragma unroll
    for (int i = 0; i < 8; i++) {
        float4 o0 = make_float4(acc[i][0] + bb[i], acc[i][1] + bb[i],
                                acc[i][2] + bb[i], acc[i][3] + bb[i]);
        float4 o1 = make_float4(acc[i][4] + bb[i], acc[i][5] + bb[i],
                                acc[i][6] + bb[i], acc[i][7] + bb[i]);
        float* dst = Yp + (size_t)(m0 + tm + i) * HW + n0 + tn;
        *(float4*)(dst)     = o0;
        *(float4*)(dst + 4) = o1;
    }
}

// ---------------------------------------------------------------------------
// Attention per (b, h): scores = Q K^T / 8 -> softmax rows -> out = attn @ V
// Q,K,V are [64][4096] slices of g_qkv. grid = (NHEADS, BATCH), 256 threads.
// ---------------------------------------------------------------------------
__global__ __launch_bounds__(256)
void attn_kernel()
{
    __shared__ float sQ[32][68];   // [n-chunk][d] transposed; 68-float stride keeps
    __shared__ float sK[32][68];   //   float4 rows 16B-aligned (68*4 = 272 B)
    __shared__ float sS[64][65];   // scores / attn weights (scalar access only)
    __shared__ float sV[64][36];   // [e][n-chunk], 36*4 = 144 B rows, 16B-aligned

    const int h   = blockIdx.x;
    const int b   = blockIdx.y;
    const int tid = threadIdx.x;

    const float* qb = g_qkv + ((size_t)b * MQKV + 0 * CDIM + h * DHEAD) * HW;
    const float* kb = g_qkv + ((size_t)b * MQKV + 1 * CDIM + h * DHEAD) * HW;
    const float* vb = g_qkv + ((size_t)b * MQKV + 2 * CDIM + h * DHEAD) * HW;
    float*       ob = g_att + ((size_t)b * CDIM + h * DHEAD) * HW;

    const int d0 = (tid >> 4) * 4;
    const int e0 = (tid & 15) * 4;
    float acc[4][4];
#pragma unroll
    for (int i = 0; i < 4; i++)
#pragma unroll
        for (int j = 0; j < 4; j++) acc[i][j] = 0.0f;

    // ---- scores = Q K^T, reduced over n in chunks of 32 ----
    for (int n0 = 0; n0 < HW; n0 += 32) {
        __syncthreads();
#pragma unroll
        for (int j = 0; j < 8; j++) {
            int idx = tid + j * 256;
            int d = idx >> 5, col = idx & 31;
            sQ[col][d] = qb[(size_t)d * HW + n0 + col];
            sK[col][d] = kb[(size_t)d * HW + n0 + col];
        }
        __syncthreads();
#pragma unroll 8
        for (int kk = 0; kk < 32; kk++) {
            float a[4], c[4];
            *(float4*)a = *(const float4*)(&sQ[kk][d0]);
            *(float4*)c = *(const float4*)(&sK[kk][e0]);
#pragma unroll
            for (int i = 0; i < 4; i++)
#pragma unroll
                for (int j = 0; j < 4; j++)
                    acc[i][j] = fmaf(a[i], c[j], acc[i][j]);
        }
    }
#pragma unroll
    for (int i = 0; i < 4; i++)
#pragma unroll
        for (int j = 0; j < 4; j++)
            sS[d0 + i][e0 + j] = acc[i][j] * 0.125f;   // / sqrt(64)
    __syncthreads();

    // ---- softmax over e (row-wise), one thread per row ----
    if (tid < 64) {
        float m = -1e30f;
#pragma unroll 8
        for (int e = 0; e < 64; e++) m = fmaxf(m, sS[tid][e]);
        float s = 0.0f;
#pragma unroll 8
        for (int e = 0; e < 64; e++) {
            float v = __expf(sS[tid][e] - m);
            sS[tid][e] = v;
            s += v;
        }
        float inv = 1.0f / s;
#pragma unroll 8
        for (int e = 0; e < 64; e++) sS[tid][e] *= inv;
    }
    __syncthreads();

    // ---- out = attn @ V, streamed over n in chunks of 32 ----
    for (int n0 = 0; n0 < HW; n0 += 32) {
        __syncthreads();
#pragma unroll
        for (int j = 0; j < 8; j++) {
            int idx = tid + j * 256;
            int e = idx >> 5, col = idx & 31;
            sV[e][col] = vb[(size_t)e * HW + n0 + col];
        }
        __syncthreads();
        // 512 float4-outputs per chunk (64 d x 8 col-groups), 2 per thread
#pragma unroll
        for (int j = 0; j < 2; j++) {
            int g  = tid + j * 256;
            int d  = g >> 3;
            int cg = (g & 7) * 4;
            float4 s4 = make_float4(0.f, 0.f, 0.f, 0.f);
#pragma unroll 16
            for (int e = 0; e < 64; e++) {
                float  w  = sS[d][e];
                float4 v4 = *(const float4*)(&sV[e][cg]);
                s4.x = fmaf(w, v4.x, s4.x);
                s4.y = fmaf(w, v4.y, s4.y);
                s4.z = fmaf(w, v4.z, s4.z);
                s4.w = fmaf(w, v4.w, s4.w);
            }
            *(float4*)(ob + (size_t)d * HW + n0 + cg) = s4;
        }
    }
}

// ---------------------------------------------------------------------------
// LayerNorm over (C,H,W) per batch element — deterministic two-pass reduce
// ---------------------------------------------------------------------------
__global__ void reduce_partial(const float* __restrict__ Y)
{
    const int b = blockIdx.y, blk = blockIdx.x;   // 64 chunks of 32768 per batch
    const float* p = Y + (size_t)b * CDIM * HW + (size_t)blk * 32768;
    float s = 0.0f, q = 0.0f;
    for (int i = threadIdx.x; i < 32768; i += 256) {
        float v = p[i];
        s += v;
        q = fmaf(v, v, q);
    }
    __shared__ float ss[256], sq[256];
    ss[threadIdx.x] = s; sq[threadIdx.x] = q;
    __syncthreads();
    for (int st = 128; st > 0; st >>= 1) {
        if (threadIdx.x < st) {
            ss[threadIdx.x] += ss[threadIdx.x + st];
            sq[threadIdx.x] += sq[threadIdx.x + st];
        }
        __syncthreads();
    }
    if (threadIdx.x == 0) {
        g_psum[b * 64 + blk] = ss[0];
        g_psq [b * 64 + blk] = sq[0];
    }
}

__global__ void finalize_stats()
{
    const int b = blockIdx.x;
    const int t = threadIdx.x;   // 64 threads
    __shared__ float ss[64], sq[64];
    ss[t] = g_psum[b * 64 + t];
    sq[t] = g_psq [b * 64 + t];
    __syncthreads();
    for (int st = 32; st > 0; st >>= 1) {
        if (t < st) { ss[t] += ss[t + st]; sq[t] += sq[t + st]; }
        __syncthreads();
    }
    if (t == 0) {
        const float inv_n = 1.0f / (float)(CDIM * HW);
        float mean = ss[0] * inv_n;
        float var  = sq[0] * inv_n - mean * mean;
        g_stats[b * 2 + 0] = mean;
        g_stats[b * 2 + 1] = rsqrtf(var + LN_EPS);
    }
}

__global__ void apply_ln(float* __restrict__ Y,
                         const float* __restrict__ gamma,
                         const float* __restrict__ beta)
{
    size_t i4 = (size_t)blockIdx.x * blockDim.x + threadIdx.x;   // float4 index
    int b = (int)(i4 >> 19);          // 512*4096/4 = 2^19 float4 per batch
    int c = (int)((i4 >> 10) & 511);  // 4096/4 = 2^10 float4 per channel
    float mean = g_stats[b * 2 + 0];
    float inv  = g_stats[b * 2 + 1];
    float g  = gamma[c] * inv;
    float bt = fmaf(-mean, g, beta[c]);
    float4 v = ((float4*)Y)[i4];
    v.x = fmaf(v.x, g, bt);
    v.y = fmaf(v.y, g, bt);
    v.z = fmaf(v.z, g, bt);
    v.w = fmaf(v.w, g, bt);
    ((float4*)Y)[i4] = v;
}

// ---------------------------------------------------------------------------
extern "C" void kernel_launch(void* const* d_in, const int* in_sizes, int n_in,
                              void* d_out, int out_size)
{
    const float* x      = (const float*)d_in[0];
    const float* w_qkv  = (const float*)d_in[1];
    const float* w_out  = (const float*)d_in[2];
    const float* b_out  = (const float*)d_in[3];
    const float* gamma  = (const float*)d_in[4];
    const float* beta   = (const float*)d_in[5];
    float* out = (float*)d_out;

    float *qkv_ptr, *att_ptr;
    cudaGetSymbolAddress((void**)&qkv_ptr, g_qkv);
    cudaGetSymbolAddress((void**)&att_ptr, g_att);

    // 1) QKV projection: [16][1536][4096] = w_qkv @ x
    gemm_wx<<<dim3(HW / 128, MQKV / 128, BATCH), 256>>>(w_qkv, x, qkv_ptr, nullptr, CDIM);

    // 2) channel-attention per (b,h)
    attn_kernel<<<dim3(NHEADS, BATCH), 256>>>();

    // 3) output projection + bias: [16][512][4096] -> d_out
    gemm_wx<<<dim3(HW / 128, CDIM / 128, BATCH), 256>>>(w_out, att_ptr, out, b_out, CDIM);

    // 4) per-batch LayerNorm over (C,H,W)
    reduce_partial<<<dim3(64, BATCH), 256>>>(out);
    finalize_stats<<<BATCH, 64>>>();
    apply_ln<<<(BATCH * CDIM * HW / 4) / 256, 256>>>(out, gamma, beta);
}

// round 6
// speedup vs baseline: 1.1841x; 1.1841x over previous
#include <cuda_runtime.h>
#include <math.h>
#include <stdint.h>

#define BATCH   16
#define CDIM    512
#define HW      4096
#define MQKV    1536
#define NHEADS  8
#define DHEAD   64
#define LN_EPS  1e-5f

// Scratch (device globals — no cudaMalloc allowed)
__device__ float g_qkv[(size_t)BATCH * MQKV * HW];   // ~402 MB
__device__ float g_att[(size_t)BATCH * CDIM * HW];   // ~134 MB
__device__ float g_psum[BATCH * 64];
__device__ float g_psq [BATCH * 64];
__device__ float g_stats[BATCH * 2];

__device__ __forceinline__ uint32_t f2tf32(float v) {
    uint32_t t;
    asm("cvt.rna.tf32.f32 %0, %1;" : "=r"(t) : "f"(v));
    return t;
}

// split x into hi (tf32) and lo (tf32 of residual)
__device__ __forceinline__ void tf32_split(float x, uint32_t& hi, uint32_t& lo) {
    hi = f2tf32(x);
    float r = x - __uint_as_float(hi);
    lo = f2tf32(r);
}

__device__ __forceinline__ void mma_tf32(float* d, const uint32_t* a,
                                         const uint32_t* b, const float* c) {
    asm volatile(
        "mma.sync.aligned.m16n8k8.row.col.f32.tf32.tf32.f32 "
        "{%0,%1,%2,%3}, {%4,%5,%6,%7}, {%8,%9}, {%10,%11,%12,%13};\n"
        : "=f"(d[0]), "=f"(d[1]), "=f"(d[2]), "=f"(d[3])
        : "r"(a[0]), "r"(a[1]), "r"(a[2]), "r"(a[3]),
          "r"(b[0]), "r"(b[1]),
          "f"(c[0]), "f"(c[1]), "f"(c[2]), "f"(c[3]));
}

// ---------------------------------------------------------------------------
// 3xTF32 compensated GEMM: Y[b][m][n] = sum_k W[m][k]*X[b][k][n] (+ bias[m])
// a*b ~= a_lo*b_hi + a_hi*b_lo + a_hi*b_hi  (effective fp32 precision)
// BM=BN=128, BK=16, 256 threads = 8 warps, warp tile 64x32 (4x4 m16n8k8).
// ---------------------------------------------------------------------------
__global__ __launch_bounds__(256)
void gemm_tf32x3(const float* __restrict__ W, const float* __restrict__ X,
                 float* __restrict__ Y, const float* __restrict__ bias, int K)
{
    __shared__ uint32_t AsH[128][20];   // [m][k], pad 20 (80B rows)
    __shared__ uint32_t AsL[128][20];
    __shared__ uint32_t BsH[16][136];   // [k][n], pad 136 (544B rows)
    __shared__ uint32_t BsL[16][136];

    const int b   = blockIdx.z;
    const int m0  = blockIdx.y * 128;
    const int n0  = blockIdx.x * 128;
    const int tid = threadIdx.x;

    const int wid  = tid >> 5;
    const int lane = tid & 31;
    const int wm   = (wid >> 2) * 64;   // 0 or 64
    const int wn   = (wid & 3) * 32;    // 0,32,64,96
    const int r    = lane >> 2;         // 0..7
    const int c    = lane & 3;          // 0..3

    const float* Wp = W + (size_t)m0 * K;
    const float* Xp = X + (size_t)b * K * HW + n0;

    float acc[4][4][4];
#pragma unroll
    for (int mt = 0; mt < 4; mt++)
#pragma unroll
        for (int nt = 0; nt < 4; nt++)
#pragma unroll
            for (int i = 0; i < 4; i++) acc[mt][nt][i] = 0.0f;

    const int ar = tid >> 2;            // 0..63 (rows ar, ar+64)
    const int ac = (tid & 3) * 4;       // 0,4,8,12
    const int br = tid >> 5;            // 0..7  (rows br, br+8)
    const int bc = (tid & 31) * 4;      // 0..124

    for (int k0 = 0; k0 < K; k0 += 16) {
        float4 a0 = *(const float4*)(Wp + (size_t)ar        * K + k0 + ac);
        float4 a1 = *(const float4*)(Wp + (size_t)(ar + 64) * K + k0 + ac);
        float4 x0 = *(const float4*)(Xp + (size_t)(k0 + br)     * HW + bc);
        float4 x1 = *(const float4*)(Xp + (size_t)(k0 + br + 8) * HW + bc);

        __syncthreads();
        {
            uint32_t h, l;
            tf32_split(a0.x, h, l); AsH[ar][ac+0] = h; AsL[ar][ac+0] = l;
            tf32_split(a0.y, h, l); AsH[ar][ac+1] = h; AsL[ar][ac+1] = l;
            tf32_split(a0.z, h, l); AsH[ar][ac+2] = h; AsL[ar][ac+2] = l;
            tf32_split(a0.w, h, l); AsH[ar][ac+3] = h; AsL[ar][ac+3] = l;
            tf32_split(a1.x, h, l); AsH[ar+64][ac+0] = h; AsL[ar+64][ac+0] = l;
            tf32_split(a1.y, h, l); AsH[ar+64][ac+1] = h; AsL[ar+64][ac+1] = l;
            tf32_split(a1.z, h, l); AsH[ar+64][ac+2] = h; AsL[ar+64][ac+2] = l;
            tf32_split(a1.w, h, l); AsH[ar+64][ac+3] = h; AsL[ar+64][ac+3] = l;

            uint4 th, tl;
            tf32_split(x0.x, th.x, tl.x); tf32_split(x0.y, th.y, tl.y);
            tf32_split(x0.z, th.z, tl.z); tf32_split(x0.w, th.w, tl.w);
            *(uint4*)(&BsH[br][bc]) = th;
            *(uint4*)(&BsL[br][bc]) = tl;
            tf32_split(x1.x, th.x, tl.x); tf32_split(x1.y, th.y, tl.y);
            tf32_split(x1.z, th.z, tl.z); tf32_split(x1.w, th.w, tl.w);
            *(uint4*)(&BsH[br+8][bc]) = th;
            *(uint4*)(&BsL[br+8][bc]) = tl;
        }
        __syncthreads();

#pragma unroll
        for (int ks = 0; ks < 16; ks += 8) {
            uint32_t afH[4][4], afL[4][4];
#pragma unroll
            for (int mt = 0; mt < 4; mt++) {
                const int m = wm + mt * 16;
                afH[mt][0] = AsH[m + r]    [ks + c];
                afH[mt][1] = AsH[m + r + 8][ks + c];
                afH[mt][2] = AsH[m + r]    [ks + c + 4];
                afH[mt][3] = AsH[m + r + 8][ks + c + 4];
                afL[mt][0] = AsL[m + r]    [ks + c];
                afL[mt][1] = AsL[m + r + 8][ks + c];
                afL[mt][2] = AsL[m + r]    [ks + c + 4];
                afL[mt][3] = AsL[m + r + 8][ks + c + 4];
            }
            uint32_t bfH[4][2], bfL[4][2];
#pragma unroll
            for (int nt = 0; nt < 4; nt++) {
                const int n = wn + nt * 8;
                bfH[nt][0] = BsH[ks + c]    [n + r];
                bfH[nt][1] = BsH[ks + c + 4][n + r];
                bfL[nt][0] = BsL[ks + c]    [n + r];
                bfL[nt][1] = BsL[ks + c + 4][n + r];
            }
            // small terms first, dominant last
#pragma unroll
            for (int mt = 0; mt < 4; mt++)
#pragma unroll
                for (int nt = 0; nt < 4; nt++) {
                    mma_tf32(acc[mt][nt], afL[mt], bfH[nt], acc[mt][nt]);
                    mma_tf32(acc[mt][nt], afH[mt], bfL[nt], acc[mt][nt]);
                    mma_tf32(acc[mt][nt], afH[mt], bfH[nt], acc[mt][nt]);
                }
        }
    }

    const int M = gridDim.y * 128;
    float* Yp = Y + (size_t)b * M * HW;
#pragma unroll
    for (int mt = 0; mt < 4; mt++) {
        const int row0 = m0 + wm + mt * 16 + r;
        const float b0v = bias ? bias[row0]     : 0.0f;
        const float b1v = bias ? bias[row0 + 8] : 0.0f;
#pragma unroll
        for (int nt = 0; nt < 4; nt++) {
            const int col = n0 + wn + nt * 8 + 2 * c;
            float2 o0 = make_float2(acc[mt][nt][0] + b0v, acc[mt][nt][1] + b0v);
            float2 o1 = make_float2(acc[mt][nt][2] + b1v, acc[mt][nt][3] + b1v);
            *(float2*)(Yp + (size_t)row0       * HW + col) = o0;
            *(float2*)(Yp + (size_t)(row0 + 8) * HW + col) = o1;
        }
    }
}

// ---------------------------------------------------------------------------
// Attention per (b, h): scores = Q K^T / 8 -> softmax rows -> out = attn @ V
// fp32 (softmax precision-sensitive; only ~8.6 GF total).
// ---------------------------------------------------------------------------
__global__ __launch_bounds__(256)
void attn_kernel()
{
    __shared__ float sQ[32][68];
    __shared__ float sK[32][68];
    __shared__ float sS[64][65];
    __shared__ float sV[64][36];

    const int h   = blockIdx.x;
    const int b   = blockIdx.y;
    const int tid = threadIdx.x;

    const float* qb = g_qkv + ((size_t)b * MQKV + 0 * CDIM + h * DHEAD) * HW;
    const float* kb = g_qkv + ((size_t)b * MQKV + 1 * CDIM + h * DHEAD) * HW;
    const float* vb = g_qkv + ((size_t)b * MQKV + 2 * CDIM + h * DHEAD) * HW;
    float*       ob = g_att + ((size_t)b * CDIM + h * DHEAD) * HW;

    const int d0 = (tid >> 4) * 4;
    const int e0 = (tid & 15) * 4;
    float acc[4][4];
#pragma unroll
    for (int i = 0; i < 4; i++)
#pragma unroll
        for (int j = 0; j < 4; j++) acc[i][j] = 0.0f;

    for (int n0 = 0; n0 < HW; n0 += 32) {
        __syncthreads();
#pragma unroll
        for (int j = 0; j < 8; j++) {
            int idx = tid + j * 256;
            int d = idx >> 5, col = idx & 31;
            sQ[col][d] = qb[(size_t)d * HW + n0 + col];
            sK[col][d] = kb[(size_t)d * HW + n0 + col];
        }
        __syncthreads();
#pragma unroll 8
        for (int kk = 0; kk < 32; kk++) {
            float a[4], cc[4];
            *(float4*)a  = *(const float4*)(&sQ[kk][d0]);
            *(float4*)cc = *(const float4*)(&sK[kk][e0]);
#pragma unroll
            for (int i = 0; i < 4; i++)
#pragma unroll
                for (int j = 0; j < 4; j++)
                    acc[i][j] = fmaf(a[i], cc[j], acc[i][j]);
        }
    }
#pragma unroll
    for (int i = 0; i < 4; i++)
#pragma unroll
        for (int j = 0; j < 4; j++)
            sS[d0 + i][e0 + j] = acc[i][j] * 0.125f;
    __syncthreads();

    if (tid < 64) {
        float m = -1e30f;
#pragma unroll 8
        for (int e = 0; e < 64; e++) m = fmaxf(m, sS[tid][e]);
        float s = 0.0f;
#pragma unroll 8
        for (int e = 0; e < 64; e++) {
            float v = __expf(sS[tid][e] - m);
            sS[tid][e] = v;
            s += v;
        }
        float inv = 1.0f / s;
#pragma unroll 8
        for (int e = 0; e < 64; e++) sS[tid][e] *= inv;
    }
    __syncthreads();

    for (int n0 = 0; n0 < HW; n0 += 32) {
        __syncthreads();
#pragma unroll
        for (int j = 0; j < 8; j++) {
            int idx = tid + j * 256;
            int e = idx >> 5, col = idx & 31;
            sV[e][col] = vb[(size_t)e * HW + n0 + col];
        }
        __syncthreads();
#pragma unroll
        for (int j = 0; j < 2; j++) {
            int g  = tid + j * 256;
            int d  = g >> 3;
            int cg = (g & 7) * 4;
            float4 s4 = make_float4(0.f, 0.f, 0.f, 0.f);
#pragma unroll 16
            for (int e = 0; e < 64; e++) {
                float  w  = sS[d][e];
                float4 v4 = *(const float4*)(&sV[e][cg]);
                s4.x = fmaf(w, v4.x, s4.x);
                s4.y = fmaf(w, v4.y, s4.y);
                s4.z = fmaf(w, v4.z, s4.z);
                s4.w = fmaf(w, v4.w, s4.w);
            }
            *(float4*)(ob + (size_t)d * HW + n0 + cg) = s4;
        }
    }
}

// ---------------------------------------------------------------------------
// LayerNorm over (C,H,W) per batch element — deterministic two-pass reduce
// ---------------------------------------------------------------------------
__global__ void reduce_partial(const float* __restrict__ Y)
{
    const int b = blockIdx.y, blk = blockIdx.x;
    const float* p = Y + (size_t)b * CDIM * HW + (size_t)blk * 32768;
    float s = 0.0f, q = 0.0f;
    for (int i = threadIdx.x; i < 32768; i += 256) {
        float v = p[i];
        s += v;
        q = fmaf(v, v, q);
    }
    __shared__ float ss[256], sq[256];
    ss[threadIdx.x] = s; sq[threadIdx.x] = q;
    __syncthreads();
    for (int st = 128; st > 0; st >>= 1) {
        if (threadIdx.x < st) {
            ss[threadIdx.x] += ss[threadIdx.x + st];
            sq[threadIdx.x] += sq[threadIdx.x + st];
        }
        __syncthreads();
    }
    if (threadIdx.x == 0) {
        g_psum[b * 64 + blk] = ss[0];
        g_psq [b * 64 + blk] = sq[0];
    }
}

__global__ void finalize_stats()
{
    const int b = blockIdx.x;
    const int t = threadIdx.x;
    __shared__ float ss[64], sq[64];
    ss[t] = g_psum[b * 64 + t];
    sq[t] = g_psq [b * 64 + t];
    __syncthreads();
    for (int st = 32; st > 0; st >>= 1) {
        if (t < st) { ss[t] += ss[t + st]; sq[t] += sq[t + st]; }
        __syncthreads();
    }
    if (t == 0) {
        const float inv_n = 1.0f / (float)(CDIM * HW);
        float mean = ss[0] * inv_n;
        float var  = sq[0] * inv_n - mean * mean;
        g_stats[b * 2 + 0] = mean;
        g_stats[b * 2 + 1] = rsqrtf(var + LN_EPS);
    }
}

__global__ void apply_ln(float* __restrict__ Y,
                         const float* __restrict__ gamma,
                         const float* __restrict__ beta)
{
    size_t i4 = (size_t)blockIdx.x * blockDim.x + threadIdx.x;
    int b = (int)(i4 >> 19);
    int c = (int)((i4 >> 10) & 511);
    float mean = g_stats[b * 2 + 0];
    float inv  = g_stats[b * 2 + 1];
    float g  = gamma[c] * inv;
    float bt = fmaf(-mean, g, beta[c]);
    float4 v = ((float4*)Y)[i4];
    v.x = fmaf(v.x, g, bt);
    v.y = fmaf(v.y, g, bt);
    v.z = fmaf(v.z, g, bt);
    v.w = fmaf(v.w, g, bt);
    ((float4*)Y)[i4] = v;
}

// ---------------------------------------------------------------------------
extern "C" void kernel_launch(void* const* d_in, const int* in_sizes, int n_in,
                              void* d_out, int out_size)
{
    const float* x      = (const float*)d_in[0];
    const float* w_qkv  = (const float*)d_in[1];
    const float* w_out  = (const float*)d_in[2];
    const float* b_out  = (const float*)d_in[3];
    const float* gamma  = (const float*)d_in[4];
    const float* beta   = (const float*)d_in[5];
    float* out = (float*)d_out;

    float *qkv_ptr, *att_ptr;
    cudaGetSymbolAddress((void**)&qkv_ptr, g_qkv);
    cudaGetSymbolAddress((void**)&att_ptr, g_att);

    // 1) QKV projection (3xTF32 tensor cores, fp32-accurate)
    gemm_tf32x3<<<dim3(HW / 128, MQKV / 128, BATCH), 256>>>(w_qkv, x, qkv_ptr, nullptr, CDIM);

    // 2) channel-attention per (b,h) — fp32
    attn_kernel<<<dim3(NHEADS, BATCH), 256>>>();

    // 3) output projection + bias (3xTF32 tensor cores)
    gemm_tf32x3<<<dim3(HW / 128, CDIM / 128, BATCH), 256>>>(w_out, att_ptr, out, b_out, CDIM);

    // 4) per-batch LayerNorm
    reduce_partial<<<dim3(64, BATCH), 256>>>(out);
    finalize_stats<<<BATCH, 64>>>();
    apply_ln<<<(BATCH * CDIM * HW / 4) / 256, 256>>>(out, gamma, beta);
}

// round 7
// speedup vs baseline: 1.5315x; 1.2935x over previous
#include <cuda_runtime.h>
#include <math.h>
#include <stdint.h>

#define BATCH   16
#define CDIM    512
#define HW      4096
#define MQKV    1536
#define NHEADS  8
#define DHEAD   64
#define LN_EPS  1e-5f
#define NCHUNK  8
#define CHUNK   (HW / NCHUNK)   // 512

// ---------------- scratch (device globals; no cudaMalloc allowed) ----------
__device__ float    g_qkv [(size_t)BATCH * MQKV * HW];   // fp32 qkv        402MB
__device__ uint32_t g_xH  [(size_t)BATCH * CDIM * HW];   // x split hi      134MB
__device__ uint32_t g_xL  [(size_t)BATCH * CDIM * HW];   // x split lo      134MB
__device__ uint32_t g_attH[(size_t)BATCH * CDIM * HW];   // attn-out hi     134MB
__device__ uint32_t g_attL[(size_t)BATCH * CDIM * HW];   // attn-out lo     134MB
__device__ uint32_t g_wqkvH[MQKV * CDIM];
__device__ uint32_t g_wqkvL[MQKV * CDIM];
__device__ uint32_t g_woutH[CDIM * CDIM];
__device__ uint32_t g_woutL[CDIM * CDIM];
__device__ float    g_scores[(size_t)BATCH * NHEADS * NCHUNK * 64 * 64];
__device__ float    g_attn  [(size_t)BATCH * NHEADS * 64 * 64];
__device__ float    g_psum[BATCH * 64];
__device__ float    g_psq [BATCH * 64];
__device__ float    g_stats[BATCH * 2];

// ---------------- helpers ---------------------------------------------------
__device__ __forceinline__ uint32_t f2tf32(float v) {
    uint32_t t;
    asm("cvt.rna.tf32.f32 %0, %1;" : "=r"(t) : "f"(v));
    return t;
}
__device__ __forceinline__ void tf32_split(float x, uint32_t& hi, uint32_t& lo) {
    hi = f2tf32(x);
    lo = f2tf32(x - __uint_as_float(hi));
}
__device__ __forceinline__ void mma_tf32(float* d, const uint32_t* a,
                                         const uint32_t* b, const float* c) {
    asm volatile(
        "mma.sync.aligned.m16n8k8.row.col.f32.tf32.tf32.f32 "
        "{%0,%1,%2,%3}, {%4,%5,%6,%7}, {%8,%9}, {%10,%11,%12,%13};\n"
        : "=f"(d[0]), "=f"(d[1]), "=f"(d[2]), "=f"(d[3])
        : "r"(a[0]), "r"(a[1]), "r"(a[2]), "r"(a[3]),
          "r"(b[0]), "r"(b[1]),
          "f"(c[0]), "f"(c[1]), "f"(c[2]), "f"(c[3]));
}
#define LDMX4(rg, addr) \
    asm volatile("ldmatrix.sync.aligned.m8n8.x4.shared.b16 {%0,%1,%2,%3}, [%4];" \
        : "=r"(rg[0]), "=r"(rg[1]), "=r"(rg[2]), "=r"(rg[3]) : "r"(addr))
#define CP_ASYNC16(dst_u32, src_ptr) \
    asm volatile("cp.async.cg.shared.global [%0], [%1], 16;" \
        :: "r"(dst_u32), "l"(src_ptr))
#define CP_COMMIT_WAIT() \
    asm volatile("cp.async.commit_group;\n cp.async.wait_group 0;" ::: "memory")

// ---------------- split fp32 -> (tf32 hi, tf32 lo) -------------------------
__global__ void split_kernel(const float* __restrict__ in,
                             uint32_t* __restrict__ hi,
                             uint32_t* __restrict__ lo, int n4)
{
    int i = blockIdx.x * blockDim.x + threadIdx.x;
    if (i >= n4) return;
    float4 v = ((const float4*)in)[i];
    uint4 h, l;
    tf32_split(v.x, h.x, l.x);
    tf32_split(v.y, h.y, l.y);
    tf32_split(v.z, h.z, l.z);
    tf32_split(v.w, h.w, l.w);
    ((uint4*)hi)[i] = h;
    ((uint4*)lo)[i] = l;
}

// ---------------------------------------------------------------------------
// 3xTF32 GEMM, pre-split operands: Y[b][m][n] = sum_k A[m][k]*B[b][k][n] (+bias)
// BM=BN=128, BK=32, 256 thr = 8 warps, warp tile 64x32, cp.async + ldmatrix.
// ---------------------------------------------------------------------------
#define GEMM_SMEM_BYTES ((128*36*2 + 32*136*2) * 4)   // 71680

__global__ __launch_bounds__(256, 2)
void gemm_tf32x3(const uint32_t* __restrict__ AH, const uint32_t* __restrict__ AL,
                 const uint32_t* __restrict__ BH, const uint32_t* __restrict__ BL,
                 float* __restrict__ Y, const float* __restrict__ bias,
                 int K, int M)
{
    extern __shared__ uint32_t sm[];
    uint32_t* AsH = sm;                    // [128][36]  (144B rows, 16B aligned)
    uint32_t* AsL = AsH + 128 * 36;
    uint32_t* BsH = AsL + 128 * 36;        // [32][136]
    uint32_t* BsL = BsH + 32 * 136;

    const int b   = blockIdx.z;
    const int m0  = blockIdx.y * 128;
    const int n0  = blockIdx.x * 128;
    const int tid = threadIdx.x;
    const int wid = tid >> 5, lane = tid & 31;
    const int wm  = (wid >> 2) * 64;
    const int wn  = (wid & 3) * 32;
    const int r   = lane >> 2, c = lane & 3;

    const uint32_t* AHp = AH + (size_t)m0 * K;
    const uint32_t* ALp = AL + (size_t)m0 * K;
    const uint32_t* BHp = BH + (size_t)b * K * HW + n0;
    const uint32_t* BLp = BL + (size_t)b * K * HW + n0;

    float acc[4][4][4];
#pragma unroll
    for (int mt = 0; mt < 4; mt++)
#pragma unroll
        for (int nt = 0; nt < 4; nt++)
#pragma unroll
            for (int i = 0; i < 4; i++) acc[mt][nt][i] = 0.0f;

    // async-copy assignments: A 128x32 (4 chunks of 32 rows), B 32x128 (4 of 8)
    const int arow = tid >> 3;            // 0..31
    const int acol = (tid & 7) * 4;       // 0..28
    const int brow = tid >> 5;            // 0..7
    const int bcol = (tid & 31) * 4;      // 0..124

    const uint32_t sAHa = (uint32_t)__cvta_generic_to_shared(AsH);
    const uint32_t sALa = (uint32_t)__cvta_generic_to_shared(AsL);
    const uint32_t sBHa = (uint32_t)__cvta_generic_to_shared(BsH);
    const uint32_t sBLa = (uint32_t)__cvta_generic_to_shared(BsL);

    // ldmatrix per-lane source row/col for A fragments
    const int lrow = (lane & 7) + ((lane >> 3) & 1) * 8;   // 0..15
    const int lcol = ((lane >> 4) & 1) * 4;                // 0 or 4
    const uint32_t aHf = sAHa + (((wm + lrow) * 36 + lcol) << 2);
    const uint32_t aLf = sALa + (((wm + lrow) * 36 + lcol) << 2);

    for (int k0 = 0; k0 < K; k0 += 32) {
        __syncthreads();   // previous tile fully consumed
#pragma unroll
        for (int i = 0; i < 4; i++) {
            const int m = arow + i * 32;
            CP_ASYNC16(sAHa + ((m * 36 + acol) << 2), AHp + (size_t)m * K + k0 + acol);
            CP_ASYNC16(sALa + ((m * 36 + acol) << 2), ALp + (size_t)m * K + k0 + acol);
        }
#pragma unroll
        for (int i = 0; i < 4; i++) {
            const int kk = brow + i * 8;
            CP_ASYNC16(sBHa + ((kk * 136 + bcol) << 2), BHp + (size_t)(k0 + kk) * HW + bcol);
            CP_ASYNC16(sBLa + ((kk * 136 + bcol) << 2), BLp + (size_t)(k0 + kk) * HW + bcol);
        }
        CP_COMMIT_WAIT();
        __syncthreads();   // tile visible to all warps

#pragma unroll
        for (int ks = 0; ks < 32; ks += 8) {
            uint32_t bfH[4][2], bfL[4][2];
#pragma unroll
            for (int nt = 0; nt < 4; nt++) {
                const int nn = wn + nt * 8 + r;
                bfH[nt][0] = BsH[(ks + c)     * 136 + nn];
                bfH[nt][1] = BsH[(ks + c + 4) * 136 + nn];
                bfL[nt][0] = BsL[(ks + c)     * 136 + nn];
                bfL[nt][1] = BsL[(ks + c + 4) * 136 + nn];
            }
#pragma unroll
            for (int mt = 0; mt < 4; mt++) {
                uint32_t aH[4], aL[4];
                LDMX4(aH, aHf + ((mt * 16 * 36 + ks) << 2));
                LDMX4(aL, aLf + ((mt * 16 * 36 + ks) << 2));
#pragma unroll
                for (int nt = 0; nt < 4; nt++) {
                    mma_tf32(acc[mt][nt], aL, bfH[nt], acc[mt][nt]);
                    mma_tf32(acc[mt][nt], aH, bfL[nt], acc[mt][nt]);
                    mma_tf32(acc[mt][nt], aH, bfH[nt], acc[mt][nt]);
                }
            }
        }
    }

    float* Yp = Y + (size_t)b * M * HW;
#pragma unroll
    for (int mt = 0; mt < 4; mt++) {
        const int row0 = m0 + wm + mt * 16 + r;
        const float b0v = bias ? bias[row0]     : 0.0f;
        const float b1v = bias ? bias[row0 + 8] : 0.0f;
#pragma unroll
        for (int nt = 0; nt < 4; nt++) {
            const int col = n0 + wn + nt * 8 + 2 * c;
            float2 o0 = make_float2(acc[mt][nt][0] + b0v, acc[mt][nt][1] + b0v);
            float2 o1 = make_float2(acc[mt][nt][2] + b1v, acc[mt][nt][3] + b1v);
            *(float2*)(Yp + (size_t)row0       * HW + col) = o0;
            *(float2*)(Yp + (size_t)(row0 + 8) * HW + col) = o1;
        }
    }
}

// ---------------------------------------------------------------------------
// Attention, 3 phases with 8x n-chunk parallelism (1024 blocks each).
// ---------------------------------------------------------------------------
// Phase 1: partial scores over n in [z*512, z*512+512)
__global__ __launch_bounds__(256)
void attn_scores()
{
    __shared__ float sQ[32][68];
    __shared__ float sK[32][68];

    const int h = blockIdx.x, b = blockIdx.y, z = blockIdx.z;
    const int tid = threadIdx.x;

    const float* qb = g_qkv + ((size_t)b * MQKV + 0 * CDIM + h * DHEAD) * HW + (size_t)z * CHUNK;
    const float* kb = g_qkv + ((size_t)b * MQKV + 1 * CDIM + h * DHEAD) * HW + (size_t)z * CHUNK;

    const int d0 = (tid >> 4) * 4;
    const int e0 = (tid & 15) * 4;
    float acc[4][4];
#pragma unroll
    for (int i = 0; i < 4; i++)
#pragma unroll
        for (int j = 0; j < 4; j++) acc[i][j] = 0.0f;

    for (int n0 = 0; n0 < CHUNK; n0 += 32) {
        __syncthreads();
#pragma unroll
        for (int j = 0; j < 8; j++) {
            int idx = tid + j * 256;
            int d = idx >> 5, col = idx & 31;
            sQ[col][d] = qb[(size_t)d * HW + n0 + col];
            sK[col][d] = kb[(size_t)d * HW + n0 + col];
        }
        __syncthreads();
#pragma unroll 8
        for (int kk = 0; kk < 32; kk++) {
            float a[4], cc[4];
            *(float4*)a  = *(const float4*)(&sQ[kk][d0]);
            *(float4*)cc = *(const float4*)(&sK[kk][e0]);
#pragma unroll
            for (int i = 0; i < 4; i++)
#pragma unroll
                for (int j = 0; j < 4; j++)
                    acc[i][j] = fmaf(a[i], cc[j], acc[i][j]);
        }
    }

    float* sp = g_scores + (((size_t)(b * NHEADS + h) * NCHUNK + z) * 64) * 64;
#pragma unroll
    for (int i = 0; i < 4; i++)
        *(float4*)(sp + (size_t)(d0 + i) * 64 + e0) =
            make_float4(acc[i][0], acc[i][1], acc[i][2], acc[i][3]);
}

// Phase 2: sum partials, scale, softmax rows. 64 threads, one per row d.
__global__ void attn_softmax()
{
    const int h = blockIdx.x, b = blockIdx.y;
    const int d = threadIdx.x;   // 0..63
    const float* sp = g_scores + ((size_t)(b * NHEADS + h) * NCHUNK * 64) * 64;

    float row[64];
#pragma unroll
    for (int e = 0; e < 64; e++) row[e] = 0.0f;
    for (int z = 0; z < NCHUNK; z++) {
        const float4* p = (const float4*)(sp + (size_t)z * 4096 + d * 64);
#pragma unroll
        for (int e4 = 0; e4 < 16; e4++) {
            float4 v = p[e4];
            row[e4 * 4 + 0] += v.x; row[e4 * 4 + 1] += v.y;
            row[e4 * 4 + 2] += v.z; row[e4 * 4 + 3] += v.w;
        }
    }
    float m = -1e30f;
#pragma unroll
    for (int e = 0; e < 64; e++) { row[e] *= 0.125f; m = fmaxf(m, row[e]); }
    float s = 0.0f;
#pragma unroll
    for (int e = 0; e < 64; e++) { row[e] = __expf(row[e] - m); s += row[e]; }
    const float inv = 1.0f / s;
    float* ap = g_attn + ((size_t)(b * NHEADS + h) * 64 + d) * 64;
#pragma unroll
    for (int e4 = 0; e4 < 16; e4++)
        ((float4*)ap)[e4] = make_float4(row[e4*4+0]*inv, row[e4*4+1]*inv,
                                        row[e4*4+2]*inv, row[e4*4+3]*inv);
}

// Phase 3: out = attn @ V over n-chunk; writes split hi/lo for GEMM2.
__global__ __launch_bounds__(256)
void attn_av()
{
    __shared__ float sA[64][65];
    __shared__ float sV[64][36];

    const int h = blockIdx.x, b = blockIdx.y, z = blockIdx.z;
    const int tid = threadIdx.x;

    const float* ap = g_attn + (size_t)(b * NHEADS + h) * 4096;
#pragma unroll
    for (int j = 0; j < 16; j++) {
        int idx = tid + j * 256;
        sA[idx >> 6][idx & 63] = ap[idx];
    }

    const float* vb = g_qkv + ((size_t)b * MQKV + 2 * CDIM + h * DHEAD) * HW + (size_t)z * CHUNK;
    const size_t obase = ((size_t)b * CDIM + h * DHEAD) * HW + (size_t)z * CHUNK;

    for (int n0 = 0; n0 < CHUNK; n0 += 32) {
        __syncthreads();
#pragma unroll
        for (int j = 0; j < 8; j++) {
            int idx = tid + j * 256;
            int e = idx >> 5, col = idx & 31;
            sV[e][col] = vb[(size_t)e * HW + n0 + col];
        }
        __syncthreads();
#pragma unroll
        for (int j = 0; j < 2; j++) {
            int g  = tid + j * 256;
            int d  = g >> 3;
            int cg = (g & 7) * 4;
            float4 s4 = make_float4(0.f, 0.f, 0.f, 0.f);
#pragma unroll 16
            for (int e = 0; e < 64; e++) {
                float  w  = sA[d][e];
                float4 v4 = *(const float4*)(&sV[e][cg]);
                s4.x = fmaf(w, v4.x, s4.x);
                s4.y = fmaf(w, v4.y, s4.y);
                s4.z = fmaf(w, v4.z, s4.z);
                s4.w = fmaf(w, v4.w, s4.w);
            }
            uint4 hh, ll;
            tf32_split(s4.x, hh.x, ll.x);
            tf32_split(s4.y, hh.y, ll.y);
            tf32_split(s4.z, hh.z, ll.z);
            tf32_split(s4.w, hh.w, ll.w);
            const size_t off = obase + (size_t)d * HW + n0 + cg;
            *(uint4*)(g_attH + off) = hh;
            *(uint4*)(g_attL + off) = ll;
        }
    }
}

// ---------------------------------------------------------------------------
// LayerNorm over (C,H,W) per batch — deterministic two-pass reduce
// ---------------------------------------------------------------------------
__global__ void reduce_partial(const float* __restrict__ Y)
{
    const int b = blockIdx.y, blk = blockIdx.x;
    const float* p = Y + (size_t)b * CDIM * HW + (size_t)blk * 32768;
    float s = 0.0f, q = 0.0f;
    for (int i = threadIdx.x; i < 32768; i += 256) {
        float v = p[i];
        s += v;
        q = fmaf(v, v, q);
    }
    __shared__ float ss[256], sq[256];
    ss[threadIdx.x] = s; sq[threadIdx.x] = q;
    __syncthreads();
    for (int st = 128; st > 0; st >>= 1) {
        if (threadIdx.x < st) {
            ss[threadIdx.x] += ss[threadIdx.x + st];
            sq[threadIdx.x] += sq[threadIdx.x + st];
        }
        __syncthreads();
    }
    if (threadIdx.x == 0) {
        g_psum[b * 64 + blk] = ss[0];
        g_psq [b * 64 + blk] = sq[0];
    }
}

__global__ void finalize_stats()
{
    const int b = blockIdx.x;
    const int t = threadIdx.x;
    __shared__ float ss[64], sq[64];
    ss[t] = g_psum[b * 64 + t];
    sq[t] = g_psq [b * 64 + t];
    __syncthreads();
    for (int st = 32; st > 0; st >>= 1) {
        if (t < st) { ss[t] += ss[t + st]; sq[t] += sq[t + st]; }
        __syncthreads();
    }
    if (t == 0) {
        const float inv_n = 1.0f / (float)(CDIM * HW);
        float mean = ss[0] * inv_n;
        float var  = sq[0] * inv_n - mean * mean;
        g_stats[b * 2 + 0] = mean;
        g_stats[b * 2 + 1] = rsqrtf(var + LN_EPS);
    }
}

__global__ void apply_ln(float* __restrict__ Y,
                         const float* __restrict__ gamma,
                         const float* __restrict__ beta)
{
    size_t i4 = (size_t)blockIdx.x * blockDim.x + threadIdx.x;
    int b = (int)(i4 >> 19);
    int c = (int)((i4 >> 10) & 511);
    float mean = g_stats[b * 2 + 0];
    float inv  = g_stats[b * 2 + 1];
    float g  = gamma[c] * inv;
    float bt = fmaf(-mean, g, beta[c]);
    float4 v = ((float4*)Y)[i4];
    v.x = fmaf(v.x, g, bt);
    v.y = fmaf(v.y, g, bt);
    v.z = fmaf(v.z, g, bt);
    v.w = fmaf(v.w, g, bt);
    ((float4*)Y)[i4] = v;
}

// ---------------------------------------------------------------------------
extern "C" void kernel_launch(void* const* d_in, const int* in_sizes, int n_in,
                              void* d_out, int out_size)
{
    const float* x      = (const float*)d_in[0];
    const float* w_qkv  = (const float*)d_in[1];
    const float* w_out  = (const float*)d_in[2];
    const float* b_out  = (const float*)d_in[3];
    const float* gamma  = (const float*)d_in[4];
    const float* beta   = (const float*)d_in[5];
    float* out = (float*)d_out;

    float    *qkv_p;
    uint32_t *xH, *xL, *attH, *attL, *wqH, *wqL, *woH, *woL;
    cudaGetSymbolAddress((void**)&qkv_p, g_qkv);
    cudaGetSymbolAddress((void**)&xH,    g_xH);
    cudaGetSymbolAddress((void**)&xL,    g_xL);
    cudaGetSymbolAddress((void**)&attH,  g_attH);
    cudaGetSymbolAddress((void**)&attL,  g_attL);
    cudaGetSymbolAddress((void**)&wqH,   g_wqkvH);
    cudaGetSymbolAddress((void**)&wqL,   g_wqkvL);
    cudaGetSymbolAddress((void**)&woH,   g_woutH);
    cudaGetSymbolAddress((void**)&woL,   g_woutL);

    cudaFuncSetAttribute(gemm_tf32x3,
                         cudaFuncAttributeMaxDynamicSharedMemorySize,
                         GEMM_SMEM_BYTES);

    // 0) split weights + input into tf32 hi/lo pairs
    split_kernel<<<(MQKV * CDIM / 4 + 255) / 256, 256>>>(w_qkv, wqH, wqL, MQKV * CDIM / 4);
    split_kernel<<<(CDIM * CDIM / 4 + 255) / 256, 256>>>(w_out, woH, woL, CDIM * CDIM / 4);
    {
        int n4 = (int)((size_t)BATCH * CDIM * HW / 4);
        split_kernel<<<(n4 + 255) / 256, 256>>>(x, xH, xL, n4);
    }

    // 1) QKV projection (3xTF32 tensor cores)
    gemm_tf32x3<<<dim3(HW / 128, MQKV / 128, BATCH), 256, GEMM_SMEM_BYTES>>>(
        wqH, wqL, xH, xL, qkv_p, nullptr, CDIM, MQKV);

    // 2) channel-attention, 8x n-chunk parallel
    attn_scores <<<dim3(NHEADS, BATCH, NCHUNK), 256>>>();
    attn_softmax<<<dim3(NHEADS, BATCH), 64>>>();
    attn_av     <<<dim3(NHEADS, BATCH, NCHUNK), 256>>>();

    // 3) output projection + bias (3xTF32)
    gemm_tf32x3<<<dim3(HW / 128, CDIM / 128, BATCH), 256, GEMM_SMEM_BYTES>>>(
        woH, woL, attH, attL, out, b_out, CDIM, CDIM);

    // 4) per-batch LayerNorm
    reduce_partial<<<dim3(64, BATCH), 256>>>(out);
    finalize_stats<<<BATCH, 64>>>();
    apply_ln<<<(BATCH * CDIM * HW / 4) / 256, 256>>>(out, gamma, beta);
}

// round 9
// speedup vs baseline: 2.4109x; 1.5741x over previous
#include <cuda_runtime.h>
#include <cuda_bf16.h>
#include <math.h>
#include <stdint.h>

#define BATCH   16
#define CDIM    512
#define HW      4096
#define MQKV    1536
#define NHEADS  8
#define DHEAD   64
#define LN_EPS  1e-5f
#define NCHUNK  8
#define CHUNK   (HW / NCHUNK)   // 512

// ---------------- scratch (device globals; no cudaMalloc allowed) ----------
__device__ float         g_qkv [(size_t)BATCH * MQKV * HW];   // fp32 qkv  402MB
__device__ __nv_bfloat16 g_xH  [(size_t)BATCH * CDIM * HW];   // 67MB
__device__ __nv_bfloat16 g_xL  [(size_t)BATCH * CDIM * HW];
__device__ __nv_bfloat16 g_attH[(size_t)BATCH * CDIM * HW];
__device__ __nv_bfloat16 g_attL[(size_t)BATCH * CDIM * HW];
__device__ __nv_bfloat16 g_wqkvH[MQKV * CDIM];
__device__ __nv_bfloat16 g_wqkvL[MQKV * CDIM];
__device__ __nv_bfloat16 g_woutH[CDIM * CDIM];
__device__ __nv_bfloat16 g_woutL[CDIM * CDIM];
__device__ float         g_scores[(size_t)BATCH * NHEADS * NCHUNK * 64 * 64];
__device__ float         g_attn  [(size_t)BATCH * NHEADS * 64 * 64];
__device__ float         g_psum[BATCH * 64];
__device__ float         g_psq [BATCH * 64];
__device__ float         g_stats[BATCH * 2];

// ---------------- helpers ---------------------------------------------------
__device__ __forceinline__ void bf16_split(float x, unsigned short& h, unsigned short& l) {
    __nv_bfloat16 hb = __float2bfloat16_rn(x);
    float r = x - __bfloat162float(hb);
    __nv_bfloat16 lb = __float2bfloat16_rn(r);
    h = __bfloat16_as_ushort(hb);
    l = __bfloat16_as_ushort(lb);
}

__device__ __forceinline__ void mma_bf16(float* d, const uint32_t* a,
                                         const uint32_t* b, const float* c) {
    asm volatile(
        "mma.sync.aligned.m16n8k16.row.col.f32.bf16.bf16.f32 "
        "{%0,%1,%2,%3}, {%4,%5,%6,%7}, {%8,%9}, {%10,%11,%12,%13};\n"
        : "=f"(d[0]), "=f"(d[1]), "=f"(d[2]), "=f"(d[3])
        : "r"(a[0]), "r"(a[1]), "r"(a[2]), "r"(a[3]),
          "r"(b[0]), "r"(b[1]),
          "f"(c[0]), "f"(c[1]), "f"(c[2]), "f"(c[3]));
}
#define LDMX4(rg, addr) \
    asm volatile("ldmatrix.sync.aligned.m8n8.x4.shared.b16 {%0,%1,%2,%3}, [%4];" \
        : "=r"(rg[0]), "=r"(rg[1]), "=r"(rg[2]), "=r"(rg[3]) : "r"(addr))
#define LDMX4T(rg, addr) \
    asm volatile("ldmatrix.sync.aligned.m8n8.x4.trans.shared.b16 {%0,%1,%2,%3}, [%4];" \
        : "=r"(rg[0]), "=r"(rg[1]), "=r"(rg[2]), "=r"(rg[3]) : "r"(addr))
#define CP_ASYNC16(dst_u32, src_ptr) \
    asm volatile("cp.async.cg.shared.global [%0], [%1], 16;" \
        :: "r"(dst_u32), "l"(src_ptr))
#define CP_COMMIT() asm volatile("cp.async.commit_group;" ::: "memory")
#define CP_WAIT1()  asm volatile("cp.async.wait_group 1;" ::: "memory")
#define CP_WAIT0()  asm volatile("cp.async.wait_group 0;" ::: "memory")

// ---------------- split fp32 -> (bf16 hi, bf16 lo) -------------------------
__global__ void split_kernel(const float* __restrict__ in,
                             __nv_bfloat16* __restrict__ hi,
                             __nv_bfloat16* __restrict__ lo, int n4)
{
    int i = blockIdx.x * blockDim.x + threadIdx.x;
    if (i >= n4) return;
    float4 v = ((const float4*)in)[i];
    unsigned short h[4], l[4];
    bf16_split(v.x, h[0], l[0]);
    bf16_split(v.y, h[1], l[1]);
    bf16_split(v.z, h[2], l[2]);
    bf16_split(v.w, h[3], l[3]);
    uint2 hp = make_uint2((uint32_t)h[0] | ((uint32_t)h[1] << 16),
                          (uint32_t)h[2] | ((uint32_t)h[3] << 16));
    uint2 lp = make_uint2((uint32_t)l[0] | ((uint32_t)l[1] << 16),
                          (uint32_t)l[2] | ((uint32_t)l[3] << 16));
    ((uint2*)hi)[i] = hp;
    ((uint2*)lo)[i] = lp;
}

// ---------------------------------------------------------------------------
// bf16x3 compensated GEMM: Y[b][m][n] = sum_k A[m][k]*B[b][k][n] (+bias)
// a*b ~= aL*bH + aH*bL + aH*bH   (fp32 accum; ~4e-5 relative)
// BM=BN=128, BK=32, 256 thr, warp tile 64x32, m16n8k16, 2-stage cp.async.
// ---------------------------------------------------------------------------
#define A_ROW   40                      // bf16 elems per A smem row (80 B)
#define B_ROW   136                     // bf16 elems per B smem row (272 B)
#define A_TILE_B (128 * A_ROW * 2)      // 10240 B
#define B_TILE_B (32 * B_ROW * 2)       // 8704 B
#define OFF_AH  0
#define OFF_AL  (A_TILE_B)
#define OFF_BH  (2 * A_TILE_B)
#define OFF_BL  (2 * A_TILE_B + B_TILE_B)
#define STAGE_B (2 * A_TILE_B + 2 * B_TILE_B)   // 37888
#define GEMM_SMEM_BYTES (2 * STAGE_B)           // 75776

__global__ __launch_bounds__(256, 2)
void gemm_bf16x3(const __nv_bfloat16* __restrict__ AH, const __nv_bfloat16* __restrict__ AL,
                 const __nv_bfloat16* __restrict__ BH, const __nv_bfloat16* __restrict__ BL,
                 float* __restrict__ Y, const float* __restrict__ bias,
                 int K, int M)
{
    extern __shared__ uint8_t sm[];
    const uint32_t sbase = (uint32_t)__cvta_generic_to_shared(sm);

    const int b   = blockIdx.z;
    const int m0  = blockIdx.y * 128;
    const int n0  = blockIdx.x * 128;
    const int tid = threadIdx.x;
    const int wid = tid >> 5, lane = tid & 31;
    const int wm  = (wid >> 2) * 64;
    const int wn  = (wid & 3) * 32;
    const int r   = lane >> 2, c = lane & 3;

    const __nv_bfloat16* AHp = AH + (size_t)m0 * K;
    const __nv_bfloat16* ALp = AL + (size_t)m0 * K;
    const __nv_bfloat16* BHp = BH + (size_t)b * K * HW + n0;
    const __nv_bfloat16* BLp = BL + (size_t)b * K * HW + n0;

    float acc[4][4][4];
#pragma unroll
    for (int mt = 0; mt < 4; mt++)
#pragma unroll
        for (int nt = 0; nt < 4; nt++)
#pragma unroll
            for (int i = 0; i < 4; i++) acc[mt][nt][i] = 0.0f;

    // cp.async assignments: A 128x32 bf16 (512 16B segs), B 32x128 (512 segs)
    const int aseg_r0 = (tid * 2)     >> 2;   // unrolled below with seg = 2*tid+i? use i*256+tid
    (void)aseg_r0;

    // ldmatrix lane offsets (bytes within a stage buffer)
    const uint32_t a_lane_off = (uint32_t)(((wm + (lane & 15)) * A_ROW + ((lane >> 4) & 1) * 8) * 2);
    const uint32_t b_lane_off = (uint32_t)(((lane & 15) * B_ROW + wn + ((lane >> 4) & 1) * 8) * 2);

    const int NITER = K >> 5;

    // ---- stage loader ----
    auto load_stage = [&](int it, int s) {
        const int k0 = it << 5;
        const uint32_t st = sbase + (uint32_t)(s * STAGE_B);
#pragma unroll
        for (int i = 0; i < 2; i++) {
            int seg = i * 256 + tid;            // A: 512 segs
            int row = seg >> 2, c16 = seg & 3;
            uint32_t d = st + (uint32_t)((row * A_ROW + c16 * 8) * 2);
            const __nv_bfloat16* sh = AHp + (size_t)row * K + k0 + c16 * 8;
            const __nv_bfloat16* sl = ALp + (size_t)row * K + k0 + c16 * 8;
            CP_ASYNC16(d + OFF_AH, sh);
            CP_ASYNC16(d + OFF_AL, sl);
        }
#pragma unroll
        for (int i = 0; i < 2; i++) {
            int seg = i * 256 + tid;            // B: 512 segs
            int row = seg >> 4, c16 = seg & 15;
            uint32_t d = st + (uint32_t)((row * B_ROW + c16 * 8) * 2);
            const __nv_bfloat16* sh = BHp + (size_t)(k0 + row) * HW + c16 * 8;
            const __nv_bfloat16* sl = BLp + (size_t)(k0 + row) * HW + c16 * 8;
            CP_ASYNC16(d + OFF_BH, sh);
            CP_ASYNC16(d + OFF_BL, sl);
        }
        CP_COMMIT();
    };

    load_stage(0, 0);

    for (int it = 0; it < NITER; it++) {
        if (it + 1 < NITER) {
            load_stage(it + 1, (it + 1) & 1);
            CP_WAIT1();
        } else {
            CP_WAIT0();
        }
        __syncthreads();

        const uint32_t st = sbase + (uint32_t)((it & 1) * STAGE_B);
        const uint32_t aH0 = st + OFF_AH + a_lane_off;
        const uint32_t aL0 = st + OFF_AL + a_lane_off;
        const uint32_t bH0 = st + OFF_BH + b_lane_off;
        const uint32_t bL0 = st + OFF_BL + b_lane_off;

#pragma unroll
        for (int ks = 0; ks < 32; ks += 16) {
            uint32_t bfH[4][2], bfL[4][2];
#pragma unroll
            for (int p = 0; p < 2; p++) {      // each x4.trans covers 2 n-tiles
                uint32_t rg[4];
                LDMX4T(rg, bH0 + (uint32_t)((ks * B_ROW + p * 16) * 2));
                bfH[2*p][0] = rg[0]; bfH[2*p][1] = rg[1];
                bfH[2*p+1][0] = rg[2]; bfH[2*p+1][1] = rg[3];
                LDMX4T(rg, bL0 + (uint32_t)((ks * B_ROW + p * 16) * 2));
                bfL[2*p][0] = rg[0]; bfL[2*p][1] = rg[1];
                bfL[2*p+1][0] = rg[2]; bfL[2*p+1][1] = rg[3];
            }
#pragma unroll
            for (int mt = 0; mt < 4; mt++) {
                uint32_t aHf[4], aLf[4];
                LDMX4(aHf, aH0 + (uint32_t)((mt * 16 * A_ROW + ks) * 2));
                LDMX4(aLf, aL0 + (uint32_t)((mt * 16 * A_ROW + ks) * 2));
#pragma unroll
                for (int nt = 0; nt < 4; nt++) {
                    mma_bf16(acc[mt][nt], aLf, bfH[nt], acc[mt][nt]);
                    mma_bf16(acc[mt][nt], aHf, bfL[nt], acc[mt][nt]);
                    mma_bf16(acc[mt][nt], aHf, bfH[nt], acc[mt][nt]);
                }
            }
        }
        __syncthreads();
    }

    float* Yp = Y + (size_t)b * M * HW;
#pragma unroll
    for (int mt = 0; mt < 4; mt++) {
        const int row0 = m0 + wm + mt * 16 + r;
        const float b0v = bias ? bias[row0]     : 0.0f;
        const float b1v = bias ? bias[row0 + 8] : 0.0f;
#pragma unroll
        for (int nt = 0; nt < 4; nt++) {
            const int col = n0 + wn + nt * 8 + 2 * c;
            float2 o0 = make_float2(acc[mt][nt][0] + b0v, acc[mt][nt][1] + b0v);
            float2 o1 = make_float2(acc[mt][nt][2] + b1v, acc[mt][nt][3] + b1v);
            *(float2*)(Yp + (size_t)row0       * HW + col) = o0;
            *(float2*)(Yp + (size_t)(row0 + 8) * HW + col) = o1;
        }
    }
}

// ---------------------------------------------------------------------------
// Attention, 3 phases with 8x n-chunk parallelism.
// ---------------------------------------------------------------------------
__global__ __launch_bounds__(256)
void attn_scores()
{
    __shared__ float sQ[32][68];
    __shared__ float sK[32][68];

    const int h = blockIdx.x, b = blockIdx.y, z = blockIdx.z;
    const int tid = threadIdx.x;

    const float* qb = g_qkv + ((size_t)b * MQKV + 0 * CDIM + h * DHEAD) * HW + (size_t)z * CHUNK;
    const float* kb = g_qkv + ((size_t)b * MQKV + 1 * CDIM + h * DHEAD) * HW + (size_t)z * CHUNK;

    const int d0 = (tid >> 4) * 4;
    const int e0 = (tid & 15) * 4;
    float acc[4][4];
#pragma unroll
    for (int i = 0; i < 4; i++)
#pragma unroll
        for (int j = 0; j < 4; j++) acc[i][j] = 0.0f;

    for (int n0 = 0; n0 < CHUNK; n0 += 32) {
        __syncthreads();
#pragma unroll
        for (int j = 0; j < 8; j++) {
            int idx = tid + j * 256;
            int d = idx >> 5, col = idx & 31;
            sQ[col][d] = qb[(size_t)d * HW + n0 + col];
            sK[col][d] = kb[(size_t)d * HW + n0 + col];
        }
        __syncthreads();
#pragma unroll 8
        for (int kk = 0; kk < 32; kk++) {
            float a[4], cc[4];
            *(float4*)a  = *(const float4*)(&sQ[kk][d0]);
            *(float4*)cc = *(const float4*)(&sK[kk][e0]);
#pragma unroll
            for (int i = 0; i < 4; i++)
#pragma unroll
                for (int j = 0; j < 4; j++)
                    acc[i][j] = fmaf(a[i], cc[j], acc[i][j]);
        }
    }

    float* sp = g_scores + (((size_t)(b * NHEADS + h) * NCHUNK + z) * 64) * 64;
#pragma unroll
    for (int i = 0; i < 4; i++)
        *(float4*)(sp + (size_t)(d0 + i) * 64 + e0) =
            make_float4(acc[i][0], acc[i][1], acc[i][2], acc[i][3]);
}

__global__ void attn_softmax()
{
    const int h = blockIdx.x, b = blockIdx.y;
    const int d = threadIdx.x;
    const float* sp = g_scores + ((size_t)(b * NHEADS + h) * NCHUNK * 64) * 64;

    float row[64];
#pragma unroll
    for (int e = 0; e < 64; e++) row[e] = 0.0f;
    for (int z = 0; z < NCHUNK; z++) {
        const float4* p = (const float4*)(sp + (size_t)z * 4096 + d * 64);
#pragma unroll
        for (int e4 = 0; e4 < 16; e4++) {
            float4 v = p[e4];
            row[e4 * 4 + 0] += v.x; row[e4 * 4 + 1] += v.y;
            row[e4 * 4 + 2] += v.z; row[e4 * 4 + 3] += v.w;
        }
    }
    float m = -1e30f;
#pragma unroll
    for (int e = 0; e < 64; e++) { row[e] *= 0.125f; m = fmaxf(m, row[e]); }
    float s = 0.0f;
#pragma unroll
    for (int e = 0; e < 64; e++) { row[e] = __expf(row[e] - m); s += row[e]; }
    const float inv = 1.0f / s;
    float* ap = g_attn + ((size_t)(b * NHEADS + h) * 64 + d) * 64;
#pragma unroll
    for (int e4 = 0; e4 < 16; e4++)
        ((float4*)ap)[e4] = make_float4(row[e4*4+0]*inv, row[e4*4+1]*inv,
                                        row[e4*4+2]*inv, row[e4*4+3]*inv);
}

// Phase 3: out = attn @ V over n-chunk; writes split bf16 hi/lo for GEMM2.
__global__ __launch_bounds__(256)
void attn_av()
{
    __shared__ float sA[64][65];
    __shared__ float sV[64][36];

    const int h = blockIdx.x, b = blockIdx.y, z = blockIdx.z;
    const int tid = threadIdx.x;

    const float* ap = g_attn + (size_t)(b * NHEADS + h) * 4096;
#pragma unroll
    for (int j = 0; j < 16; j++) {
        int idx = tid + j * 256;
        sA[idx >> 6][idx & 63] = ap[idx];
    }

    const float* vb = g_qkv + ((size_t)b * MQKV + 2 * CDIM + h * DHEAD) * HW + (size_t)z * CHUNK;
    const size_t obase = ((size_t)b * CDIM + h * DHEAD) * HW + (size_t)z * CHUNK;

    for (int n0 = 0; n0 < CHUNK; n0 += 32) {
        __syncthreads();
#pragma unroll
        for (int j = 0; j < 8; j++) {
            int idx = tid + j * 256;
            int e = idx >> 5, col = idx & 31;
            sV[e][col] = vb[(size_t)e * HW + n0 + col];
        }
        __syncthreads();
#pragma unroll
        for (int j = 0; j < 2; j++) {
            int g  = tid + j * 256;
            int d  = g >> 3;
            int cg = (g & 7) * 4;
            float4 s4 = make_float4(0.f, 0.f, 0.f, 0.f);
#pragma unroll 16
            for (int e = 0; e < 64; e++) {
                float  w  = sA[d][e];
                float4 v4 = *(const float4*)(&sV[e][cg]);
                s4.x = fmaf(w, v4.x, s4.x);
                s4.y = fmaf(w, v4.y, s4.y);
                s4.z = fmaf(w, v4.z, s4.z);
                s4.w = fmaf(w, v4.w, s4.w);
            }
            unsigned short hh[4], ll[4];
            bf16_split(s4.x, hh[0], ll[0]);
            bf16_split(s4.y, hh[1], ll[1]);
            bf16_split(s4.z, hh[2], ll[2]);
            bf16_split(s4.w, hh[3], ll[3]);
            const size_t off = obase + (size_t)d * HW + n0 + cg;
            *(uint2*)(g_attH + off) = make_uint2((uint32_t)hh[0] | ((uint32_t)hh[1] << 16),
                                                 (uint32_t)hh[2] | ((uint32_t)hh[3] << 16));
            *(uint2*)(g_attL + off) = make_uint2((uint32_t)ll[0] | ((uint32_t)ll[1] << 16),
                                                 (uint32_t)ll[2] | ((uint32_t)ll[3] << 16));
        }
    }
}

// ---------------------------------------------------------------------------
// LayerNorm over (C,H,W) per batch — deterministic two-pass reduce
// ---------------------------------------------------------------------------
__global__ void reduce_partial(const float* __restrict__ Y)
{
    const int b = blockIdx.y, blk = blockIdx.x;
    const float* p = Y + (size_t)b * CDIM * HW + (size_t)blk * 32768;
    float s = 0.0f, q = 0.0f;
    for (int i = threadIdx.x; i < 32768; i += 256) {
        float v = p[i];
        s += v;
        q = fmaf(v, v, q);
    }
    __shared__ float ss[256], sq[256];
    ss[threadIdx.x] = s; sq[threadIdx.x] = q;
    __syncthreads();
    for (int st = 128; st > 0; st >>= 1) {
        if (threadIdx.x < st) {
            ss[threadIdx.x] += ss[threadIdx.x + st];
            sq[threadIdx.x] += sq[threadIdx.x + st];
        }
        __syncthreads();
    }
    if (threadIdx.x == 0) {
        g_psum[b * 64 + blk] = ss[0];
        g_psq [b * 64 + blk] = sq[0];
    }
}

__global__ void finalize_stats()
{
    const int b = blockIdx.x;
    const int t = threadIdx.x;
    __shared__ float ss[64], sq[64];
    ss[t] = g_psum[b * 64 + t];
    sq[t] = g_psq [b * 64 + t];
    __syncthreads();
    for (int st = 32; st > 0; st >>= 1) {
        if (t < st) { ss[t] += ss[t + st]; sq[t] += sq[t + st]; }
        __syncthreads();
    }
    if (t == 0) {
        const float inv_n = 1.0f / (float)(CDIM * HW);
        float mean = ss[0] * inv_n;
        float var  = sq[0] * inv_n - mean * mean;
        g_stats[b * 2 + 0] = mean;
        g_stats[b * 2 + 1] = rsqrtf(var + LN_EPS);
    }
}

__global__ void apply_ln(float* __restrict__ Y,
                         const float* __restrict__ gamma,
                         const float* __restrict__ beta)
{
    size_t i4 = (size_t)blockIdx.x * blockDim.x + threadIdx.x;
    int b = (int)(i4 >> 19);
    int c = (int)((i4 >> 10) & 511);
    float mean = g_stats[b * 2 + 0];
    float inv  = g_stats[b * 2 + 1];
    float g  = gamma[c] * inv;
    float bt = fmaf(-mean, g, beta[c]);
    float4 v = ((float4*)Y)[i4];
    v.x = fmaf(v.x, g, bt);
    v.y = fmaf(v.y, g, bt);
    v.z = fmaf(v.z, g, bt);
    v.w = fmaf(v.w, g, bt);
    ((float4*)Y)[i4] = v;
}

// ---------------------------------------------------------------------------
extern "C" void kernel_launch(void* const* d_in, const int* in_sizes, int n_in,
                              void* d_out, int out_size)
{
    const float* x      = (const float*)d_in[0];
    const float* w_qkv  = (const float*)d_in[1];
    const float* w_out  = (const float*)d_in[2];
    const float* b_out  = (const float*)d_in[3];
    const float* gamma  = (const float*)d_in[4];
    const float* beta   = (const float*)d_in[5];
    float* out = (float*)d_out;

    float *qkv_p;
    __nv_bfloat16 *xH, *xL, *attH, *attL, *wqH, *wqL, *woH, *woL;
    cudaGetSymbolAddress((void**)&qkv_p, g_qkv);
    cudaGetSymbolAddress((void**)&xH,    g_xH);
    cudaGetSymbolAddress((void**)&xL,    g_xL);
    cudaGetSymbolAddress((void**)&attH,  g_attH);
    cudaGetSymbolAddress((void**)&attL,  g_attL);
    cudaGetSymbolAddress((void**)&wqH,   g_wqkvH);
    cudaGetSymbolAddress((void**)&wqL,   g_wqkvL);
    cudaGetSymbolAddress((void**)&woH,   g_woutH);
    cudaGetSymbolAddress((void**)&woL,   g_woutL);

    cudaFuncSetAttribute(gemm_bf16x3,
                         cudaFuncAttributeMaxDynamicSharedMemorySize,
                         GEMM_SMEM_BYTES);

    // 0) split weights + input into bf16 hi/lo pairs
    split_kernel<<<(MQKV * CDIM / 4 + 255) / 256, 256>>>(w_qkv, wqH, wqL, MQKV * CDIM / 4);
    split_kernel<<<(CDIM * CDIM / 4 + 255) / 256, 256>>>(w_out, woH, woL, CDIM * CDIM / 4);
    {
        int n4 = (int)((size_t)BATCH * CDIM * HW / 4);
        split_kernel<<<(n4 + 255) / 256, 256>>>(x, xH, xL, n4);
    }

    // 1) QKV projection (bf16x3 tensor cores)
    gemm_bf16x3<<<dim3(HW / 128, MQKV / 128, BATCH), 256, GEMM_SMEM_BYTES>>>(
        wqH, wqL, xH, xL, qkv_p, nullptr, CDIM, MQKV);

    // 2) channel-attention, 8x n-chunk parallel
    attn_scores <<<dim3(NHEADS, BATCH, NCHUNK), 256>>>();
    attn_softmax<<<dim3(NHEADS, BATCH), 64>>>();
    attn_av     <<<dim3(NHEADS, BATCH, NCHUNK), 256>>>();

    // 3) output projection + bias (bf16x3)
    gemm_bf16x3<<<dim3(HW / 128, CDIM / 128, BATCH), 256, GEMM_SMEM_BYTES>>>(
        woH, woL, attH, attL, out, b_out, CDIM, CDIM);

    // 4) per-batch LayerNorm
    reduce_partial<<<dim3(64, BATCH), 256>>>(out);
    finalize_stats<<<BATCH, 64>>>();
    apply_ln<<<(BATCH * CDIM * HW / 4) / 256, 256>>>(out, gamma, beta);
}

// round 13
// speedup vs baseline: 2.9563x; 1.2262x over previous
#include <cuda_runtime.h>
#include <cuda_bf16.h>
#include <math.h>
#include <stdint.h>

#define BATCH   16
#define CDIM    512
#define HW      4096
#define MQKV    1536
#define NHEADS  8
#define DHEAD   64
#define LN_EPS  1e-5f
#define NCHUNK  8
#define CHUNK   (HW / NCHUNK)   // 512

// ---------------- scratch (device globals; no cudaMalloc allowed) ----------
__device__ __nv_bfloat16 g_qkvH[(size_t)BATCH * MQKV * HW];  // qkv hi  201MB
__device__ __nv_bfloat16 g_qkvL[(size_t)BATCH * MQKV * HW];  // qkv lo  201MB
__device__ __nv_bfloat16 g_xH  [(size_t)BATCH * CDIM * HW];  // x hi [b][c][n]
__device__ __nv_bfloat16 g_xL  [(size_t)BATCH * CDIM * HW];
__device__ __nv_bfloat16 g_attH[(size_t)BATCH * CDIM * HW];  // attn-out hi [b][c][n]
__device__ __nv_bfloat16 g_attL[(size_t)BATCH * CDIM * HW];
__device__ __nv_bfloat16 g_wqkvH[MQKV * CDIM];
__device__ __nv_bfloat16 g_wqkvL[MQKV * CDIM];
__device__ __nv_bfloat16 g_woutH[CDIM * CDIM];
__device__ __nv_bfloat16 g_woutL[CDIM * CDIM];
__device__ float         g_scores[(size_t)BATCH * NHEADS * NCHUNK * 64 * 64];
__device__ float         g_attn  [(size_t)BATCH * NHEADS * 64 * 64];
__device__ float         g_psum[BATCH * 64];
__device__ float         g_psq [BATCH * 64];
__device__ float         g_stats[BATCH * 2];

// ---------------- helpers ---------------------------------------------------
__device__ __forceinline__ void bf16_split(float x, unsigned short& h, unsigned short& l) {
    __nv_bfloat16 hb = __float2bfloat16_rn(x);
    float r = x - __bfloat162float(hb);
    __nv_bfloat16 lb = __float2bfloat16_rn(r);
    h = __bfloat16_as_ushort(hb);
    l = __bfloat16_as_ushort(lb);
}

__device__ __forceinline__ void mma_bf16(float* d, const uint32_t* a,
                                         const uint32_t* b, const float* c) {
    asm volatile(
        "mma.sync.aligned.m16n8k16.row.col.f32.bf16.bf16.f32 "
        "{%0,%1,%2,%3}, {%4,%5,%6,%7}, {%8,%9}, {%10,%11,%12,%13};\n"
        : "=f"(d[0]), "=f"(d[1]), "=f"(d[2]), "=f"(d[3])
        : "r"(a[0]), "r"(a[1]), "r"(a[2]), "r"(a[3]),
          "r"(b[0]), "r"(b[1]),
          "f"(c[0]), "f"(c[1]), "f"(c[2]), "f"(c[3]));
}
#define LDMX4(rg, addr) \
    asm volatile("ldmatrix.sync.aligned.m8n8.x4.shared.b16 {%0,%1,%2,%3}, [%4];" \
        : "=r"(rg[0]), "=r"(rg[1]), "=r"(rg[2]), "=r"(rg[3]) : "r"(addr))
#define LDMX4T(rg, addr) \
    asm volatile("ldmatrix.sync.aligned.m8n8.x4.trans.shared.b16 {%0,%1,%2,%3}, [%4];" \
        : "=r"(rg[0]), "=r"(rg[1]), "=r"(rg[2]), "=r"(rg[3]) : "r"(addr))
#define CP_ASYNC16(dst_u32, src_ptr) \
    asm volatile("cp.async.cg.shared.global [%0], [%1], 16;" \
        :: "r"(dst_u32), "l"(src_ptr))
#define CP_COMMIT() asm volatile("cp.async.commit_group;" ::: "memory")
#define CP_WAIT0()  asm volatile("cp.async.wait_group 0;" ::: "memory")

// ---------------- split fp32 -> (bf16 hi, bf16 lo) -------------------------
__global__ void split_kernel(const float* __restrict__ in,
                             __nv_bfloat16* __restrict__ hi,
                             __nv_bfloat16* __restrict__ lo, int n4)
{
    int i = blockIdx.x * blockDim.x + threadIdx.x;
    if (i >= n4) return;
    float4 v = ((const float4*)in)[i];
    unsigned short h[4], l[4];
    bf16_split(v.x, h[0], l[0]);
    bf16_split(v.y, h[1], l[1]);
    bf16_split(v.z, h[2], l[2]);
    bf16_split(v.w, h[3], l[3]);
    ((uint2*)hi)[i] = make_uint2((uint32_t)h[0] | ((uint32_t)h[1] << 16),
                                 (uint32_t)h[2] | ((uint32_t)h[3] << 16));
    ((uint2*)lo)[i] = make_uint2((uint32_t)l[0] | ((uint32_t)l[1] << 16),
                                 (uint32_t)l[2] | ((uint32_t)l[3] << 16));
}

// ---------------------------------------------------------------------------
// bf16x3 compensated GEMM: Y[b][m][n] = sum_k A[m][k]*B[b][k][n]
// BM=BN=128, BK=32, 256 thr, warp tile 64x32, m16n8k16, race-free 2-stage.
// Output: either fp32 (+bias) to Yf, or bf16 hi/lo split to YH/YL.
// ---------------------------------------------------------------------------
#define A_ROW   40                      // bf16 elems per A smem row (80 B)
#define B_ROW   136                     // bf16 elems per B smem row (272 B)
#define A_TILE_B (128 * A_ROW * 2)      // 10240 B
#define B_TILE_B (32 * B_ROW * 2)       // 8704 B
#define OFF_AH  0
#define OFF_AL  (A_TILE_B)
#define OFF_BH  (2 * A_TILE_B)
#define OFF_BL  (2 * A_TILE_B + B_TILE_B)
#define STAGE_B (2 * A_TILE_B + 2 * B_TILE_B)   // 37888
#define GEMM_SMEM_BYTES (2 * STAGE_B)           // 75776

__global__ __launch_bounds__(256, 2)
void gemm_bf16x3(const __nv_bfloat16* __restrict__ AH, const __nv_bfloat16* __restrict__ AL,
                 const __nv_bfloat16* __restrict__ BH, const __nv_bfloat16* __restrict__ BL,
                 float* __restrict__ Yf,
                 __nv_bfloat16* __restrict__ YH, __nv_bfloat16* __restrict__ YL,
                 const float* __restrict__ bias, int K, int M)
{
    extern __shared__ uint8_t sm[];
    const uint32_t sbase = (uint32_t)__cvta_generic_to_shared(sm);

    const int b   = blockIdx.z;
    const int m0  = blockIdx.y * 128;
    const int n0  = blockIdx.x * 128;
    const int tid = threadIdx.x;
    const int wid = tid >> 5, lane = tid & 31;
    const int wm  = (wid >> 2) * 64;
    const int wn  = (wid & 3) * 32;
    const int r   = lane >> 2, c = lane & 3;

    const __nv_bfloat16* AHp = AH + (size_t)m0 * K;
    const __nv_bfloat16* ALp = AL + (size_t)m0 * K;
    const __nv_bfloat16* BHp = BH + (size_t)b * K * HW + n0;
    const __nv_bfloat16* BLp = BL + (size_t)b * K * HW + n0;

    float acc[4][4][4];
#pragma unroll
    for (int mt = 0; mt < 4; mt++)
#pragma unroll
        for (int nt = 0; nt < 4; nt++)
#pragma unroll
            for (int i = 0; i < 4; i++) acc[mt][nt][i] = 0.0f;

    const uint32_t a_lane_off = (uint32_t)(((wm + (lane & 15)) * A_ROW + ((lane >> 4) & 1) * 8) * 2);
    const uint32_t b_lane_off = (uint32_t)(((lane & 15) * B_ROW + wn + ((lane >> 4) & 1) * 8) * 2);

    const int NITER = K >> 5;

    auto load_stage = [&](int it) {
        const int k0 = it << 5;
        const uint32_t st = sbase + (uint32_t)((it & 1) * STAGE_B);
#pragma unroll
        for (int i = 0; i < 2; i++) {
            int seg = i * 256 + tid;            // A: 512 16B segs
            int row = seg >> 2, c16 = seg & 3;
            uint32_t d = st + (uint32_t)((row * A_ROW + c16 * 8) * 2);
            size_t go = (size_t)row * K + k0 + c16 * 8;
            CP_ASYNC16(d + OFF_AH, AHp + go);
            CP_ASYNC16(d + OFF_AL, ALp + go);
        }
#pragma unroll
        for (int i = 0; i < 2; i++) {
            int seg = i * 256 + tid;            // B: 512 segs
            int row = seg >> 4, c16 = seg & 15;
            uint32_t d = st + (uint32_t)((row * B_ROW + c16 * 8) * 2);
            size_t go = (size_t)(k0 + row) * HW + c16 * 8;
            CP_ASYNC16(d + OFF_BH, BHp + go);
            CP_ASYNC16(d + OFF_BL, BLp + go);
        }
        CP_COMMIT();
    };

    load_stage(0);

    for (int it = 0; it < NITER; it++) {
        CP_WAIT0();
        __syncthreads();
        if (it + 1 < NITER) load_stage(it + 1);

        const uint32_t st = sbase + (uint32_t)((it & 1) * STAGE_B);
        const uint32_t aH0 = st + OFF_AH + a_lane_off;
        const uint32_t aL0 = st + OFF_AL + a_lane_off;
        const uint32_t bH0 = st + OFF_BH + b_lane_off;
        const uint32_t bL0 = st + OFF_BL + b_lane_off;

#pragma unroll
        for (int ks = 0; ks < 32; ks += 16) {
            uint32_t bfH[4][2], bfL[4][2];
#pragma unroll
            for (int p = 0; p < 2; p++) {
                uint32_t rg[4];
                LDMX4T(rg, bH0 + (uint32_t)((ks * B_ROW + p * 16) * 2));
                bfH[2*p][0] = rg[0]; bfH[2*p][1] = rg[1];
                bfH[2*p+1][0] = rg[2]; bfH[2*p+1][1] = rg[3];
                LDMX4T(rg, bL0 + (uint32_t)((ks * B_ROW + p * 16) * 2));
                bfL[2*p][0] = rg[0]; bfL[2*p][1] = rg[1];
                bfL[2*p+1][0] = rg[2]; bfL[2*p+1][1] = rg[3];
            }
#pragma unroll
            for (int mt = 0; mt < 4; mt++) {
                uint32_t aHf[4], aLf[4];
                LDMX4(aHf, aH0 + (uint32_t)((mt * 16 * A_ROW + ks) * 2));
                LDMX4(aLf, aL0 + (uint32_t)((mt * 16 * A_ROW + ks) * 2));
#pragma unroll
                for (int nt = 0; nt < 4; nt++) {
                    mma_bf16(acc[mt][nt], aLf, bfH[nt], acc[mt][nt]);
                    mma_bf16(acc[mt][nt], aHf, bfL[nt], acc[mt][nt]);
                    mma_bf16(acc[mt][nt], aHf, bfH[nt], acc[mt][nt]);
                }
            }
        }
    }

    if (Yf) {
        float* Yp = Yf + (size_t)b * M * HW;
#pragma unroll
        for (int mt = 0; mt < 4; mt++) {
            const int row0 = m0 + wm + mt * 16 + r;
            const float b0v = bias ? bias[row0]     : 0.0f;
            const float b1v = bias ? bias[row0 + 8] : 0.0f;
#pragma unroll
            for (int nt = 0; nt < 4; nt++) {
                const int col = n0 + wn + nt * 8 + 2 * c;
                *(float2*)(Yp + (size_t)row0       * HW + col) =
                    make_float2(acc[mt][nt][0] + b0v, acc[mt][nt][1] + b0v);
                *(float2*)(Yp + (size_t)(row0 + 8) * HW + col) =
                    make_float2(acc[mt][nt][2] + b1v, acc[mt][nt][3] + b1v);
            }
        }
    } else {
#pragma unroll
        for (int mt = 0; mt < 4; mt++) {
            const int row0 = m0 + wm + mt * 16 + r;
#pragma unroll
            for (int nt = 0; nt < 4; nt++) {
                const int col = n0 + wn + nt * 8 + 2 * c;
                unsigned short h0, l0, h1, l1;
                size_t o0 = ((size_t)b * M + row0) * HW + col;
                size_t o1 = ((size_t)b * M + row0 + 8) * HW + col;
                bf16_split(acc[mt][nt][0], h0, l0);
                bf16_split(acc[mt][nt][1], h1, l1);
                *(uint32_t*)&YH[o0] = (uint32_t)h0 | ((uint32_t)h1 << 16);
                *(uint32_t*)&YL[o0] = (uint32_t)l0 | ((uint32_t)l1 << 16);
                bf16_split(acc[mt][nt][2], h0, l0);
                bf16_split(acc[mt][nt][3], h1, l1);
                *(uint32_t*)&YH[o1] = (uint32_t)h0 | ((uint32_t)h1 << 16);
                *(uint32_t*)&YL[o1] = (uint32_t)l0 | ((uint32_t)l1 << 16);
            }
        }
    }
}

// ---------------------------------------------------------------------------
// Attention phase 1 (tensor): partial scores[d][e] = sum_n Q[d][n]*K[e][n]
// Q,K bf16 hi/lo [row][n]; A and B both plain ldmatrix (B is [N][K] row-major).
// Block (h, b, z): contraction over n in [z*512, z*512+512). 256 thr, 8 warps.
// ---------------------------------------------------------------------------
#define SC_ROW 40   // 64-row tiles, k32, pad to 40 (80 B rows)

__global__ __launch_bounds__(256)
void attn_scores_mma()
{
    __shared__ __nv_bfloat16 sT[2][4][64 * SC_ROW];  // [stage][QH,QL,KH,KL]

    const int h = blockIdx.x, b = blockIdx.y, z = blockIdx.z;
    const int tid = threadIdx.x;
    const int wid = tid >> 5, lane = tid & 31;
    const int wm = (wid >> 1) * 16;     // 4 m-rows of warps
    const int wn = (wid & 1) * 32;      // 2 n-cols
    const int r = lane >> 2, c = lane & 3;

    const uint32_t sb = (uint32_t)__cvta_generic_to_shared(&sT[0][0][0]);
    const size_t qrow = (size_t)b * MQKV + h * DHEAD;           // Q rows
    const size_t krow = (size_t)b * MQKV + CDIM + h * DHEAD;    // K rows
    const __nv_bfloat16* QH = g_qkvH + qrow * HW + (size_t)z * CHUNK;
    const __nv_bfloat16* QL = g_qkvL + qrow * HW + (size_t)z * CHUNK;
    const __nv_bfloat16* KH = g_qkvH + krow * HW + (size_t)z * CHUNK;
    const __nv_bfloat16* KL = g_qkvL + krow * HW + (size_t)z * CHUNK;

    const uint32_t MAT = 64 * SC_ROW * 2;       // 5120 B
    const uint32_t STG = 4 * MAT;               // 20480 B

    float acc[4][4];
#pragma unroll
    for (int nt = 0; nt < 4; nt++)
#pragma unroll
        for (int i = 0; i < 4; i++) acc[nt][i] = 0.0f;

    auto load_stage = [&](int it) {
        const int k0 = it << 5;
        const uint32_t st = sb + (uint32_t)((it & 1) * STG);
        int row = tid >> 2, k8 = (tid & 3) * 8;
        uint32_t d = st + (uint32_t)((row * SC_ROW + k8) * 2);
        size_t go = (size_t)row * HW + k0 + k8;
        CP_ASYNC16(d,           QH + go);
        CP_ASYNC16(d + MAT,     QL + go);
        CP_ASYNC16(d + 2 * MAT, KH + go);
        CP_ASYNC16(d + 3 * MAT, KL + go);
        CP_COMMIT();
    };

    const uint32_t a_off = (uint32_t)(((wm + (lane & 15)) * SC_ROW + ((lane >> 4) & 1) * 8) * 2);

    load_stage(0);
    const int NITER = CHUNK / 32;   // 16
    for (int it = 0; it < NITER; it++) {
        CP_WAIT0();
        __syncthreads();
        if (it + 1 < NITER) load_stage(it + 1);

        const uint32_t st = sb + (uint32_t)((it & 1) * STG);
#pragma unroll
        for (int ks = 0; ks < 32; ks += 16) {
            uint32_t aH[4], aL[4];
            LDMX4(aH, st +           a_off + (uint32_t)(ks * 2));
            LDMX4(aL, st + MAT +     a_off + (uint32_t)(ks * 2));
            uint32_t bH[4][2], bL[4][2];
#pragma unroll
            for (int p = 0; p < 2; p++) {
                uint32_t boff = (uint32_t)(((wn + p * 16 + (lane & 15)) * SC_ROW
                                            + ((lane >> 4) & 1) * 8 + ks) * 2);
                uint32_t rg[4];
                LDMX4(rg, st + 2 * MAT + boff);
                bH[2*p][0] = rg[0]; bH[2*p][1] = rg[2];
                bH[2*p+1][0] = rg[1]; bH[2*p+1][1] = rg[3];
                LDMX4(rg, st + 3 * MAT + boff);
                bL[2*p][0] = rg[0]; bL[2*p][1] = rg[2];
                bL[2*p+1][0] = rg[1]; bL[2*p+1][1] = rg[3];
            }
#pragma unroll
            for (int nt = 0; nt < 4; nt++) {
                mma_bf16(acc[nt], aL, bH[nt], acc[nt]);
                mma_bf16(acc[nt], aH, bL[nt], acc[nt]);
                mma_bf16(acc[nt], aH, bH[nt], acc[nt]);
            }
        }
    }

    float* sp = g_scores + (((size_t)(b * NHEADS + h) * NCHUNK + z) * 64) * 64;
#pragma unroll
    for (int nt = 0; nt < 4; nt++) {
        const int e = wn + nt * 8 + 2 * c;
        *(float2*)(sp + (size_t)(wm + r)     * 64 + e) = make_float2(acc[nt][0], acc[nt][1]);
        *(float2*)(sp + (size_t)(wm + r + 8) * 64 + e) = make_float2(acc[nt][2], acc[nt][3]);
    }
}

// ---------------------------------------------------------------------------
// Attention phase 2: sum partials, scale, softmax rows (fp32). 64 thr/block.
// ---------------------------------------------------------------------------
__global__ void attn_softmax()
{
    const int h = blockIdx.x, b = blockIdx.y;
    const int d = threadIdx.x;
    const float* sp = g_scores + ((size_t)(b * NHEADS + h) * NCHUNK * 64) * 64;

    float row[64];
#pragma unroll
    for (int e = 0; e < 64; e++) row[e] = 0.0f;
    for (int z = 0; z < NCHUNK; z++) {
        const float4* p = (const float4*)(sp + (size_t)z * 4096 + d * 64);
#pragma unroll
        for (int e4 = 0; e4 < 16; e4++) {
            float4 v = p[e4];
            row[e4 * 4 + 0] += v.x; row[e4 * 4 + 1] += v.y;
            row[e4 * 4 + 2] += v.z; row[e4 * 4 + 3] += v.w;
        }
    }
    float m = -1e30f;
#pragma unroll
    for (int e = 0; e < 64; e++) { row[e] *= 0.125f; m = fmaxf(m, row[e]); }
    float s = 0.0f;
#pragma unroll
    for (int e = 0; e < 64; e++) { row[e] = __expf(row[e] - m); s += row[e]; }
    const float inv = 1.0f / s;
    float* ap = g_attn + ((size_t)(b * NHEADS + h) * 64 + d) * 64;
#pragma unroll
    for (int e4 = 0; e4 < 16; e4++)
        ((float4*)ap)[e4] = make_float4(row[e4*4+0]*inv, row[e4*4+1]*inv,
                                        row[e4*4+2]*inv, row[e4*4+3]*inv);
}

// ---------------------------------------------------------------------------
// Attention phase 3 (tensor): out[d][n] = sum_e attn[d][e] * V[e][n]
// A = attn (split in-kernel), B = V [e][n] via ldmatrix.trans (R8 pattern).
// Block (h, b, z): output n in [z*512, ...), 4 sub-tiles of 128. 256 thr.
// ---------------------------------------------------------------------------
#define AV_AROW 72                         // attn rows padded (144 B)
#define AV_A_B  (64 * AV_AROW * 2)         // 9216
#define AV_VSTG (64 * B_ROW * 2)           // 17408 per precision
#define AV_STG  (2 * AV_VSTG)              // 34816
#define AV_SMEM (2 * AV_A_B + 2 * AV_STG)  // 88064

__global__ __launch_bounds__(256)
void attn_av_mma()
{
    extern __shared__ uint8_t sm[];
    const uint32_t sb = (uint32_t)__cvta_generic_to_shared(sm);
    __nv_bfloat16* sAH = (__nv_bfloat16*)sm;
    __nv_bfloat16* sAL = (__nv_bfloat16*)(sm + AV_A_B);
    const uint32_t VBASE = sb + 2 * AV_A_B;

    const int h = blockIdx.x, b = blockIdx.y, z = blockIdx.z;
    const int tid = threadIdx.x;
    const int wid = tid >> 5, lane = tid & 31;
    const int wm = (wid >> 1) * 16;
    const int wn = (wid & 1) * 64;
    const int r = lane >> 2, c = lane & 3;

    // load + split attn weights once
    const float* ap = g_attn + (size_t)(b * NHEADS + h) * 4096;
#pragma unroll
    for (int j = 0; j < 16; j++) {
        int idx = tid + j * 256;
        int d = idx >> 6, e = idx & 63;
        unsigned short hh, ll;
        bf16_split(ap[idx], hh, ll);
        sAH[d * AV_AROW + e] = __ushort_as_bfloat16(hh);
        sAL[d * AV_AROW + e] = __ushort_as_bfloat16(ll);
    }

    const size_t vrow = (size_t)b * MQKV + 2 * CDIM + h * DHEAD;
    const __nv_bfloat16* VH = g_qkvH + vrow * HW + (size_t)z * CHUNK;
    const __nv_bfloat16* VL = g_qkvL + vrow * HW + (size_t)z * CHUNK;

    auto load_stage = [&](int it) {
        const int n0 = it << 7;
        const uint32_t st = VBASE + (uint32_t)((it & 1) * AV_STG);
#pragma unroll
        for (int i = 0; i < 4; i++) {
            int seg = i * 256 + tid;          // 1024 segs per precision
            int row = seg >> 4, n8 = (seg & 15) * 8;
            uint32_t d = st + (uint32_t)((row * B_ROW + n8) * 2);
            size_t go = (size_t)row * HW + n0 + n8;
            CP_ASYNC16(d,           VH + go);
            CP_ASYNC16(d + AV_VSTG, VL + go);
        }
        CP_COMMIT();
    };

    const uint32_t a_off = (uint32_t)(((wm + (lane & 15)) * AV_AROW + ((lane >> 4) & 1) * 8) * 2);
    const uint32_t b_lane = (uint32_t)(((lane & 15) * B_ROW + wn + ((lane >> 4) & 1) * 8) * 2);

    load_stage(0);
    for (int it = 0; it < 4; it++) {
        CP_WAIT0();
        __syncthreads();
        if (it + 1 < 4) load_stage(it + 1);

        float acc[8][4];
#pragma unroll
        for (int nt = 0; nt < 8; nt++)
#pragma unroll
            for (int i = 0; i < 4; i++) acc[nt][i] = 0.0f;

        const uint32_t st = VBASE + (uint32_t)((it & 1) * AV_STG);
#pragma unroll
        for (int ks = 0; ks < 64; ks += 16) {
            uint32_t aH[4], aL[4];
            LDMX4(aH, sb +          a_off + (uint32_t)(ks * 2));
            LDMX4(aL, sb + AV_A_B + a_off + (uint32_t)(ks * 2));
            uint32_t bH[8][2], bL[8][2];
#pragma unroll
            for (int p = 0; p < 4; p++) {
                uint32_t rg[4];
                LDMX4T(rg, st + b_lane + (uint32_t)((ks * B_ROW + p * 16) * 2));
                bH[2*p][0] = rg[0]; bH[2*p][1] = rg[1];
                bH[2*p+1][0] = rg[2]; bH[2*p+1][1] = rg[3];
                LDMX4T(rg, st + AV_VSTG + b_lane + (uint32_t)((ks * B_ROW + p * 16) * 2));
                bL[2*p][0] = rg[0]; bL[2*p][1] = rg[1];
                bL[2*p+1][0] = rg[2]; bL[2*p+1][1] = rg[3];
            }
#pragma unroll
            for (int nt = 0; nt < 8; nt++) {
                mma_bf16(acc[nt], aL, bH[nt], acc[nt]);
                mma_bf16(acc[nt], aH, bL[nt], acc[nt]);
                mma_bf16(acc[nt], aH, bH[nt], acc[nt]);
            }
        }

        // write split bf16 hi/lo to [b][c][n]
        const size_t crow = (size_t)b * CDIM + h * DHEAD;
        const int nbase = z * CHUNK + it * 128;
#pragma unroll
        for (int nt = 0; nt < 8; nt++) {
            const int col = nbase + wn + nt * 8 + 2 * c;
            unsigned short h0, l0, h1, l1;
            size_t o0 = (crow + wm + r)     * HW + col;
            size_t o1 = (crow + wm + r + 8) * HW + col;
            bf16_split(acc[nt][0], h0, l0);
            bf16_split(acc[nt][1], h1, l1);
            *(uint32_t*)&g_attH[o0] = (uint32_t)h0 | ((uint32_t)h1 << 16);
            *(uint32_t*)&g_attL[o0] = (uint32_t)l0 | ((uint32_t)l1 << 16);
            bf16_split(acc[nt][2], h0, l0);
            bf16_split(acc[nt][3], h1, l1);
            *(uint32_t*)&g_attH[o1] = (uint32_t)h0 | ((uint32_t)h1 << 16);
            *(uint32_t*)&g_attL[o1] = (uint32_t)l0 | ((uint32_t)l1 << 16);
        }
    }
}

// ---------------------------------------------------------------------------
// LayerNorm over (C,H,W) per batch — deterministic two-pass reduce
// ---------------------------------------------------------------------------
__global__ void reduce_partial(const float* __restrict__ Y)
{
    const int b = blockIdx.y, blk = blockIdx.x;
    const float* p = Y + (size_t)b * CDIM * HW + (size_t)blk * 32768;
    float s = 0.0f, q = 0.0f;
    for (int i = threadIdx.x; i < 32768; i += 256) {
        float v = p[i];
        s += v;
        q = fmaf(v, v, q);
    }
    __shared__ float ss[256], sq[256];
    ss[threadIdx.x] = s; sq[threadIdx.x] = q;
    __syncthreads();
    for (int st = 128; st > 0; st >>= 1) {
        if (threadIdx.x < st) {
            ss[threadIdx.x] += ss[threadIdx.x + st];
            sq[threadIdx.x] += sq[threadIdx.x + st];
        }
        __syncthreads();
    }
    if (threadIdx.x == 0) {
        g_psum[b * 64 + blk] = ss[0];
        g_psq [b * 64 + blk] = sq[0];
    }
}

__global__ void finalize_stats()
{
    const int b = blockIdx.x;
    const int t = threadIdx.x;
    __shared__ float ss[64], sq[64];
    ss[t] = g_psum[b * 64 + t];
    sq[t] = g_psq [b * 64 + t];
    __syncthreads();
    for (int st = 32; st > 0; st >>= 1) {
        if (t < st) { ss[t] += ss[t + st]; sq[t] += sq[t + st]; }
        __syncthreads();
    }
    if (t == 0) {
        const float inv_n = 1.0f / (float)(CDIM * HW);
        float mean = ss[0] * inv_n;
        float var  = sq[0] * inv_n - mean * mean;
        g_stats[b * 2 + 0] = mean;
        g_stats[b * 2 + 1] = rsqrtf(var + LN_EPS);
    }
}

__global__ void apply_ln(float* __restrict__ Y,
                         const float* __restrict__ gamma,
                         const float* __restrict__ beta)
{
    size_t i4 = (size_t)blockIdx.x * blockDim.x + threadIdx.x;
    int b = (int)(i4 >> 19);
    int c = (int)((i4 >> 10) & 511);
    float mean = g_stats[b * 2 + 0];
    float inv  = g_stats[b * 2 + 1];
    float g  = gamma[c] * inv;
    float bt = fmaf(-mean, g, beta[c]);
    float4 v = ((float4*)Y)[i4];
    v.x = fmaf(v.x, g, bt);
    v.y = fmaf(v.y, g, bt);
    v.z = fmaf(v.z, g, bt);
    v.w = fmaf(v.w, g, bt);
    ((float4*)Y)[i4] = v;
}

// ---------------------------------------------------------------------------
extern "C" void kernel_launch(void* const* d_in, const int* in_sizes, int n_in,
                              void* d_out, int out_size)
{
    const float* x      = (const float*)d_in[0];
    const float* w_qkv  = (const float*)d_in[1];
    const float* w_out  = (const float*)d_in[2];
    const float* b_out  = (const float*)d_in[3];
    const float* gamma  = (const float*)d_in[4];
    const float* beta   = (const float*)d_in[5];
    float* out = (float*)d_out;

    __nv_bfloat16 *qkvH, *qkvL, *xH, *xL, *attH, *attL, *wqH, *wqL, *woH, *woL;
    cudaGetSymbolAddress((void**)&qkvH, g_qkvH);
    cudaGetSymbolAddress((void**)&qkvL, g_qkvL);
    cudaGetSymbolAddress((void**)&xH,   g_xH);
    cudaGetSymbolAddress((void**)&xL,   g_xL);
    cudaGetSymbolAddress((void**)&attH, g_attH);
    cudaGetSymbolAddress((void**)&attL, g_attL);
    cudaGetSymbolAddress((void**)&wqH,  g_wqkvH);
    cudaGetSymbolAddress((void**)&wqL,  g_wqkvL);
    cudaGetSymbolAddress((void**)&woH,  g_woutH);
    cudaGetSymbolAddress((void**)&woL,  g_woutL);

    cudaFuncSetAttribute(gemm_bf16x3,
                         cudaFuncAttributeMaxDynamicSharedMemorySize, GEMM_SMEM_BYTES);
    cudaFuncSetAttribute(attn_av_mma,
                         cudaFuncAttributeMaxDynamicSharedMemorySize, AV_SMEM);

    // 0) split weights + input into bf16 hi/lo pairs
    split_kernel<<<(MQKV * CDIM / 4 + 255) / 256, 256>>>(w_qkv, wqH, wqL, MQKV * CDIM / 4);
    split_kernel<<<(CDIM * CDIM / 4 + 255) / 256, 256>>>(w_out, woH, woL, CDIM * CDIM / 4);
    {
        int n4 = (int)((size_t)BATCH * CDIM * HW / 4);
        split_kernel<<<(n4 + 255) / 256, 256>>>(x, xH, xL, n4);
    }

    // 1) QKV projection — output written directly as bf16 hi/lo
    gemm_bf16x3<<<dim3(HW / 128, MQKV / 128, BATCH), 256, GEMM_SMEM_BYTES>>>(
        wqH, wqL, xH, xL, nullptr, qkvH, qkvL, nullptr, CDIM, MQKV);

    // 2) channel-attention on tensor cores
    attn_scores_mma<<<dim3(NHEADS, BATCH, NCHUNK), 256>>>();
    attn_softmax   <<<dim3(NHEADS, BATCH), 64>>>();
    attn_av_mma    <<<dim3(NHEADS, BATCH, NCHUNK), 256, AV_SMEM>>>();

    // 3) output projection + bias (fp32 output)
    gemm_bf16x3<<<dim3(HW / 128, CDIM / 128, BATCH), 256, GEMM_SMEM_BYTES>>>(
        woH, woL, attH, attL, out, nullptr, nullptr, b_out, CDIM, CDIM);

    // 4) per-batch LayerNorm
    reduce_partial<<<dim3(64, BATCH), 256>>>(out);
    finalize_stats<<<BATCH, 64>>>();
    apply_ln<<<(BATCH * CDIM * HW / 4) / 256, 256>>>(out, gamma, beta);
}

// round 16
// speedup vs baseline: 3.9834x; 1.3475x over previous
#include <cuda_runtime.h>
#include <cuda_bf16.h>
#include <math.h>
#include <stdint.h>

#define BATCH   16
#define CDIM    512
#define HW      4096
#define MQKV    1536
#define NHEADS  8
#define DHEAD   64
#define LN_EPS  1e-5f

// ---------------- scratch (device globals; no cudaMalloc allowed) ----------
__device__ __nv_bfloat16 g_xH  [(size_t)BATCH * CDIM * HW];   // x hi [b][c][n]
__device__ __nv_bfloat16 g_xL  [(size_t)BATCH * CDIM * HW];
__device__ __nv_bfloat16 g_wqkvH[MQKV * CDIM];
__device__ __nv_bfloat16 g_wqkvL[MQKV * CDIM];
__device__ __nv_bfloat16 g_woutH[CDIM * CDIM];
__device__ __nv_bfloat16 g_woutL[CDIM * CDIM];
__device__ __nv_bfloat16 g_wvtH [CDIM * CDIM];   // W_v transposed
__device__ __nv_bfloat16 g_wvtL [CDIM * CDIM];
__device__ __nv_bfloat16 g_GH [(size_t)BATCH * CDIM * CDIM];  // Gram = x x^T
__device__ __nv_bfloat16 g_GL [(size_t)BATCH * CDIM * CDIM];
__device__ __nv_bfloat16 g_UTH[(size_t)BATCH * CDIM * CDIM];  // (Wk G)
__device__ __nv_bfloat16 g_UTL[(size_t)BATCH * CDIM * CDIM];
__device__ float         g_S  [(size_t)BATCH * CDIM * CDIM];  // Wq G Wk^T (full)
__device__ __nv_bfloat16 g_AbdH[(size_t)BATCH * CDIM * CDIM]; // block-diag attn
__device__ __nv_bfloat16 g_AbdL[(size_t)BATCH * CDIM * CDIM];
__device__ __nv_bfloat16 g_MTH[(size_t)BATCH * CDIM * CDIM];  // (A Wv)^T
__device__ __nv_bfloat16 g_MTL[(size_t)BATCH * CDIM * CDIM];
__device__ __nv_bfloat16 g_PH [(size_t)BATCH * CDIM * CDIM];  // W_out A Wv
__device__ __nv_bfloat16 g_PL [(size_t)BATCH * CDIM * CDIM];
__device__ float         g_psum[BATCH * 64];
__device__ float         g_psq [BATCH * 64];
__device__ float         g_stats[BATCH * 2];

// ---------------- helpers ---------------------------------------------------
__device__ __forceinline__ void bf16_split(float x, unsigned short& h, unsigned short& l) {
    __nv_bfloat16 hb = __float2bfloat16_rn(x);
    float r = x - __bfloat162float(hb);
    __nv_bfloat16 lb = __float2bfloat16_rn(r);
    h = __bfloat16_as_ushort(hb);
    l = __bfloat16_as_ushort(lb);
}

__device__ __forceinline__ void mma_bf16(float* d, const uint32_t* a,
                                         const uint32_t* b, const float* c) {
    asm volatile(
        "mma.sync.aligned.m16n8k16.row.col.f32.bf16.bf16.f32 "
        "{%0,%1,%2,%3}, {%4,%5,%6,%7}, {%8,%9}, {%10,%11,%12,%13};\n"
        : "=f"(d[0]), "=f"(d[1]), "=f"(d[2]), "=f"(d[3])
        : "r"(a[0]), "r"(a[1]), "r"(a[2]), "r"(a[3]),
          "r"(b[0]), "r"(b[1]),
          "f"(c[0]), "f"(c[1]), "f"(c[2]), "f"(c[3]));
}
#define LDMX4(rg, addr) \
    asm volatile("ldmatrix.sync.aligned.m8n8.x4.shared.b16 {%0,%1,%2,%3}, [%4];" \
        : "=r"(rg[0]), "=r"(rg[1]), "=r"(rg[2]), "=r"(rg[3]) : "r"(addr))
#define LDMX4T(rg, addr) \
    asm volatile("ldmatrix.sync.aligned.m8n8.x4.trans.shared.b16 {%0,%1,%2,%3}, [%4];" \
        : "=r"(rg[0]), "=r"(rg[1]), "=r"(rg[2]), "=r"(rg[3]) : "r"(addr))
#define CP_ASYNC16(dst_u32, src_ptr) \
    asm volatile("cp.async.cg.shared.global [%0], [%1], 16;" \
        :: "r"(dst_u32), "l"(src_ptr))
#define CP_COMMIT() asm volatile("cp.async.commit_group;" ::: "memory")
#define CP_WAIT0()  asm volatile("cp.async.wait_group 0;" ::: "memory")

// ---------------- split fp32 -> (bf16 hi, bf16 lo) -------------------------
__global__ void split_kernel(const float* __restrict__ in,
                             __nv_bfloat16* __restrict__ hi,
                             __nv_bfloat16* __restrict__ lo, int n4)
{
    int i = blockIdx.x * blockDim.x + threadIdx.x;
    if (i >= n4) return;
    float4 v = ((const float4*)in)[i];
    unsigned short h[4], l[4];
    bf16_split(v.x, h[0], l[0]);
    bf16_split(v.y, h[1], l[1]);
    bf16_split(v.z, h[2], l[2]);
    bf16_split(v.w, h[3], l[3]);
    ((uint2*)hi)[i] = make_uint2((uint32_t)h[0] | ((uint32_t)h[1] << 16),
                                 (uint32_t)h[2] | ((uint32_t)h[3] << 16));
    ((uint2*)lo)[i] = make_uint2((uint32_t)l[0] | ((uint32_t)l[1] << 16),
                                 (uint32_t)l[2] | ((uint32_t)l[3] << 16));
}

// ---------------- transpose-split 512x512 (for Wv) -------------------------
__global__ void transpose_split_512(const float* __restrict__ w,
                                    __nv_bfloat16* __restrict__ th,
                                    __nv_bfloat16* __restrict__ tl)
{
    __shared__ float t[32][33];
    const int r0 = blockIdx.y * 32, c0 = blockIdx.x * 32;
    const int tx = threadIdx.x, ty = threadIdx.y;   // (32, 8)
#pragma unroll
    for (int i = 0; i < 4; i++)
        t[ty + i * 8][tx] = w[(size_t)(r0 + ty + i * 8) * CDIM + c0 + tx];
    __syncthreads();
#pragma unroll
    for (int i = 0; i < 4; i++) {
        float v = t[tx][ty + i * 8];
        unsigned short h, l;
        bf16_split(v, h, l);
        size_t dst = (size_t)(c0 + ty + i * 8) * CDIM + r0 + tx;
        th[dst] = __ushort_as_bfloat16(h);
        tl[dst] = __ushort_as_bfloat16(l);
    }
}

// ---------------------------------------------------------------------------
// nt GEMM (bf16x3): C[b][m][n] = sum_k A[b][m][k] * B[b][n][k]
// Both operands K-major rows. 128x128 tile, BK=32, 256 thr, warp 64x32.
// Output: fp32 (outF) or split bf16 (outH/outL). ldc = row stride of C.
// ---------------------------------------------------------------------------
#define NT_ROW   40
#define NT_MAT_B (128 * NT_ROW * 2)       // 10240
#define NT_STG   (4 * NT_MAT_B)           // 40960 (AH AL BH BL)
#define NT_SMEM  (2 * NT_STG)             // 81920

__global__ __launch_bounds__(256, 2)
void gemm_nt128(const __nv_bfloat16* __restrict__ AH, const __nv_bfloat16* __restrict__ AL,
                size_t aStr,
                const __nv_bfloat16* __restrict__ BH, const __nv_bfloat16* __restrict__ BL,
                size_t bStr, int K,
                float* __restrict__ outF,
                __nv_bfloat16* __restrict__ outH, __nv_bfloat16* __restrict__ outL,
                size_t oStr, int ldc)
{
    extern __shared__ uint8_t sm[];
    const uint32_t sb = (uint32_t)__cvta_generic_to_shared(sm);

    const int b  = blockIdx.z;
    const int n0 = blockIdx.x * 128;
    const int m0 = blockIdx.y * 128;
    const int tid = threadIdx.x;
    const int wid = tid >> 5, lane = tid & 31;
    const int wm = (wid >> 2) * 64;
    const int wn = (wid & 3) * 32;
    const int r = lane >> 2, c = lane & 3;

    const __nv_bfloat16* AHp = AH + b * aStr + (size_t)m0 * K;
    const __nv_bfloat16* ALp = AL + b * aStr + (size_t)m0 * K;
    const __nv_bfloat16* BHp = BH + b * bStr + (size_t)n0 * K;
    const __nv_bfloat16* BLp = BL + b * bStr + (size_t)n0 * K;

    float acc[4][4][4];
#pragma unroll
    for (int mt = 0; mt < 4; mt++)
#pragma unroll
        for (int nt = 0; nt < 4; nt++)
#pragma unroll
            for (int i = 0; i < 4; i++) acc[mt][nt][i] = 0.0f;

    auto load_stage = [&](int it) {
        const int k0 = it << 5;
        const uint32_t st = sb + (uint32_t)((it & 1) * NT_STG);
#pragma unroll
        for (int i = 0; i < 2; i++) {
            int seg = i * 256 + tid;            // 512 16B segs per matrix
            int row = seg >> 2, c16 = seg & 3;
            uint32_t d = st + (uint32_t)((row * NT_ROW + c16 * 8) * 2);
            size_t go = (size_t)row * K + k0 + c16 * 8;
            CP_ASYNC16(d,                AHp + go);
            CP_ASYNC16(d + NT_MAT_B,     ALp + go);
            CP_ASYNC16(d + 2 * NT_MAT_B, BHp + go);
            CP_ASYNC16(d + 3 * NT_MAT_B, BLp + go);
        }
        CP_COMMIT();
    };

    const uint32_t a_off = (uint32_t)(((wm + (lane & 15)) * NT_ROW + ((lane >> 4) & 1) * 8) * 2);

    load_stage(0);
    const int NITER = K >> 5;
    for (int it = 0; it < NITER; it++) {
        CP_WAIT0();
        __syncthreads();
        if (it + 1 < NITER) load_stage(it + 1);

        const uint32_t st = sb + (uint32_t)((it & 1) * NT_STG);
#pragma unroll
        for (int ks = 0; ks < 32; ks += 16) {
            // B fragments: plain ldmatrix on [n][k] rows + register swap
            uint32_t bH[4][2], bL[4][2];
#pragma unroll
            for (int p = 0; p < 2; p++) {
                uint32_t boff = (uint32_t)(((wn + p * 16 + (lane & 15)) * NT_ROW
                                            + ((lane >> 4) & 1) * 8 + ks) * 2);
                uint32_t rg[4];
                LDMX4(rg, st + 2 * NT_MAT_B + boff);
                bH[2*p][0] = rg[0]; bH[2*p][1] = rg[2];
                bH[2*p+1][0] = rg[1]; bH[2*p+1][1] = rg[3];
                LDMX4(rg, st + 3 * NT_MAT_B + boff);
                bL[2*p][0] = rg[0]; bL[2*p][1] = rg[2];
                bL[2*p+1][0] = rg[1]; bL[2*p+1][1] = rg[3];
            }
#pragma unroll
            for (int mt = 0; mt < 4; mt++) {
                uint32_t aH[4], aL[4];
                uint32_t ao = a_off + (uint32_t)((mt * 16 * NT_ROW + ks) * 2);
                LDMX4(aH, st + ao);
                LDMX4(aL, st + NT_MAT_B + ao);
#pragma unroll
                for (int nt = 0; nt < 4; nt++) {
                    mma_bf16(acc[mt][nt], aL, bH[nt], acc[mt][nt]);
                    mma_bf16(acc[mt][nt], aH, bL[nt], acc[mt][nt]);
                    mma_bf16(acc[mt][nt], aH, bH[nt], acc[mt][nt]);
                }
            }
        }
    }

    if (outF) {
        float* Cp = outF + b * oStr;
#pragma unroll
        for (int mt = 0; mt < 4; mt++) {
            const int row0 = m0 + wm + mt * 16 + r;
#pragma unroll
            for (int nt = 0; nt < 4; nt++) {
                const int col = n0 + wn + nt * 8 + 2 * c;
                *(float2*)(Cp + (size_t)row0       * ldc + col) =
                    make_float2(acc[mt][nt][0], acc[mt][nt][1]);
                *(float2*)(Cp + (size_t)(row0 + 8) * ldc + col) =
                    make_float2(acc[mt][nt][2], acc[mt][nt][3]);
            }
        }
    } else {
#pragma unroll
        for (int mt = 0; mt < 4; mt++) {
            const int row0 = m0 + wm + mt * 16 + r;
#pragma unroll
            for (int nt = 0; nt < 4; nt++) {
                const int col = n0 + wn + nt * 8 + 2 * c;
                unsigned short h0, l0, h1, l1;
                size_t o0 = b * oStr + (size_t)row0 * ldc + col;
                size_t o1 = b * oStr + (size_t)(row0 + 8) * ldc + col;
                bf16_split(acc[mt][nt][0], h0, l0);
                bf16_split(acc[mt][nt][1], h1, l1);
                *(uint32_t*)&outH[o0] = (uint32_t)h0 | ((uint32_t)h1 << 16);
                *(uint32_t*)&outL[o0] = (uint32_t)l0 | ((uint32_t)l1 << 16);
                bf16_split(acc[mt][nt][2], h0, l0);
                bf16_split(acc[mt][nt][3], h1, l1);
                *(uint32_t*)&outH[o1] = (uint32_t)h0 | ((uint32_t)h1 << 16);
                *(uint32_t*)&outL[o1] = (uint32_t)l0 | ((uint32_t)l1 << 16);
            }
        }
    }
}

// ---------------------------------------------------------------------------
// nt-trans GEMM (final): Y[b][m][n] = sum_k A[b][m][k]*B[b][k][n] + bias[m]
// A K-major rows (batched); B [K][HW] row-major (ldmatrix.trans). fp32 out.
// ---------------------------------------------------------------------------
#define A_ROW   40
#define B_ROW   136
#define A_TILE_B (128 * A_ROW * 2)
#define B_TILE_B (32 * B_ROW * 2)
#define OFF_AH  0
#define OFF_AL  (A_TILE_B)
#define OFF_BH  (2 * A_TILE_B)
#define OFF_BL  (2 * A_TILE_B + B_TILE_B)
#define STAGE_B (2 * A_TILE_B + 2 * B_TILE_B)
#define GEMM_SMEM_BYTES (2 * STAGE_B)

__global__ __launch_bounds__(256, 2)
void gemm_bf16x3(const __nv_bfloat16* __restrict__ AH, const __nv_bfloat16* __restrict__ AL,
                 size_t aStr,
                 const __nv_bfloat16* __restrict__ BH, const __nv_bfloat16* __restrict__ BL,
                 float* __restrict__ Yf, const float* __restrict__ bias, int K, int M)
{
    extern __shared__ uint8_t sm[];
    const uint32_t sbase = (uint32_t)__cvta_generic_to_shared(sm);

    const int b   = blockIdx.z;
    const int m0  = blockIdx.y * 128;
    const int n0  = blockIdx.x * 128;
    const int tid = threadIdx.x;
    const int wid = tid >> 5, lane = tid & 31;
    const int wm  = (wid >> 2) * 64;
    const int wn  = (wid & 3) * 32;
    const int r   = lane >> 2, c = lane & 3;

    const __nv_bfloat16* AHp = AH + b * aStr + (size_t)m0 * K;
    const __nv_bfloat16* ALp = AL + b * aStr + (size_t)m0 * K;
    const __nv_bfloat16* BHp = BH + (size_t)b * K * HW + n0;
    const __nv_bfloat16* BLp = BL + (size_t)b * K * HW + n0;

    float acc[4][4][4];
#pragma unroll
    for (int mt = 0; mt < 4; mt++)
#pragma unroll
        for (int nt = 0; nt < 4; nt++)
#pragma unroll
            for (int i = 0; i < 4; i++) acc[mt][nt][i] = 0.0f;

    const uint32_t a_lane_off = (uint32_t)(((wm + (lane & 15)) * A_ROW + ((lane >> 4) & 1) * 8) * 2);
    const uint32_t b_lane_off = (uint32_t)(((lane & 15) * B_ROW + wn + ((lane >> 4) & 1) * 8) * 2);

    const int NITER = K >> 5;

    auto load_stage = [&](int it) {
        const int k0 = it << 5;
        const uint32_t st = sbase + (uint32_t)((it & 1) * STAGE_B);
#pragma unroll
        for (int i = 0; i < 2; i++) {
            int seg = i * 256 + tid;
            int row = seg >> 2, c16 = seg & 3;
            uint32_t d = st + (uint32_t)((row * A_ROW + c16 * 8) * 2);
            size_t go = (size_t)row * K + k0 + c16 * 8;
            CP_ASYNC16(d + OFF_AH, AHp + go);
            CP_ASYNC16(d + OFF_AL, ALp + go);
        }
#pragma unroll
        for (int i = 0; i < 2; i++) {
            int seg = i * 256 + tid;
            int row = seg >> 4, c16 = seg & 15;
            uint32_t d = st + (uint32_t)((row * B_ROW + c16 * 8) * 2);
            size_t go = (size_t)(k0 + row) * HW + c16 * 8;
            CP_ASYNC16(d + OFF_BH, BHp + go);
            CP_ASYNC16(d + OFF_BL, BLp + go);
        }
        CP_COMMIT();
    };

    load_stage(0);

    for (int it = 0; it < NITER; it++) {
        CP_WAIT0();
        __syncthreads();
        if (it + 1 < NITER) load_stage(it + 1);

        const uint32_t st = sbase + (uint32_t)((it & 1) * STAGE_B);
        const uint32_t aH0 = st + OFF_AH + a_lane_off;
        const uint32_t aL0 = st + OFF_AL + a_lane_off;
        const uint32_t bH0 = st + OFF_BH + b_lane_off;
        const uint32_t bL0 = st + OFF_BL + b_lane_off;

#pragma unroll
        for (int ks = 0; ks < 32; ks += 16) {
            uint32_t bfH[4][2], bfL[4][2];
#pragma unroll
            for (int p = 0; p < 2; p++) {
                uint32_t rg[4];
                LDMX4T(rg, bH0 + (uint32_t)((ks * B_ROW + p * 16) * 2));
                bfH[2*p][0] = rg[0]; bfH[2*p][1] = rg[1];
                bfH[2*p+1][0] = rg[2]; bfH[2*p+1][1] = rg[3];
                LDMX4T(rg, bL0 + (uint32_t)((ks * B_ROW + p * 16) * 2));
                bfL[2*p][0] = rg[0]; bfL[2*p][1] = rg[1];
                bfL[2*p+1][0] = rg[2]; bfL[2*p+1][1] = rg[3];
            }
#pragma unroll
            for (int mt = 0; mt < 4; mt++) {
                uint32_t aHf[4], aLf[4];
                LDMX4(aHf, aH0 + (uint32_t)((mt * 16 * A_ROW + ks) * 2));
                LDMX4(aLf, aL0 + (uint32_t)((mt * 16 * A_ROW + ks) * 2));
#pragma unroll
                for (int nt = 0; nt < 4; nt++) {
                    mma_bf16(acc[mt][nt], aLf, bfH[nt], acc[mt][nt]);
                    mma_bf16(acc[mt][nt], aHf, bfL[nt], acc[mt][nt]);
                    mma_bf16(acc[mt][nt], aHf, bfH[nt], acc[mt][nt]);
                }
            }
        }
    }

    float* Yp = Yf + (size_t)b * M * HW;
#pragma unroll
    for (int mt = 0; mt < 4; mt++) {
        const int row0 = m0 + wm + mt * 16 + r;
        const float b0v = bias ? bias[row0]     : 0.0f;
        const float b1v = bias ? bias[row0 + 8] : 0.0f;
#pragma unroll
        for (int nt = 0; nt < 4; nt++) {
            const int col = n0 + wn + nt * 8 + 2 * c;
            *(float2*)(Yp + (size_t)row0       * HW + col) =
                make_float2(acc[mt][nt][0] + b0v, acc[mt][nt][1] + b0v);
            *(float2*)(Yp + (size_t)(row0 + 8) * HW + col) =
                make_float2(acc[mt][nt][2] + b1v, acc[mt][nt][3] + b1v);
        }
    }
}

// ---------------------------------------------------------------------------
// Softmax over diagonal 64x64 blocks of S; writes block-diagonal attn matrix
// (bf16 hi/lo, zero off-diagonal). grid (NHEADS, BATCH), 64 threads.
// ---------------------------------------------------------------------------
__global__ void softmax_blockdiag()
{
    const int h = blockIdx.x, b = blockIdx.y;
    const int d = threadIdx.x;   // 0..63
    const float* srow = g_S + ((size_t)b * CDIM + h * DHEAD + d) * CDIM + h * DHEAD;

    float row[64];
    float m = -1e30f;
#pragma unroll
    for (int e = 0; e < 64; e++) { row[e] = srow[e] * 0.125f; m = fmaxf(m, row[e]); }
    float s = 0.0f;
#pragma unroll
    for (int e = 0; e < 64; e++) { row[e] = __expf(row[e] - m); s += row[e]; }
    const float inv = 1.0f / s;

    __nv_bfloat16* rh = g_AbdH + ((size_t)b * CDIM + h * DHEAD + d) * CDIM;
    __nv_bfloat16* rl = g_AbdL + ((size_t)b * CDIM + h * DHEAD + d) * CDIM;
    // zero entire row (uint2 = 4 bf16)
#pragma unroll 8
    for (int j = 0; j < CDIM / 4; j++) {
        ((uint2*)rh)[j] = make_uint2(0u, 0u);
        ((uint2*)rl)[j] = make_uint2(0u, 0u);
    }
    // fill head block
#pragma unroll
    for (int e4 = 0; e4 < 16; e4++) {
        unsigned short hh[4], ll[4];
#pragma unroll
        for (int q = 0; q < 4; q++) bf16_split(row[e4 * 4 + q] * inv, hh[q], ll[q]);
        ((uint2*)(rh + h * DHEAD))[e4] = make_uint2((uint32_t)hh[0] | ((uint32_t)hh[1] << 16),
                                                    (uint32_t)hh[2] | ((uint32_t)hh[3] << 16));
        ((uint2*)(rl + h * DHEAD))[e4] = make_uint2((uint32_t)ll[0] | ((uint32_t)ll[1] << 16),
                                                    (uint32_t)ll[2] | ((uint32_t)ll[3] << 16));
    }
}

// ---------------------------------------------------------------------------
// LayerNorm over (C,H,W) per batch — deterministic two-pass reduce
// ---------------------------------------------------------------------------
__global__ void reduce_partial(const float* __restrict__ Y)
{
    const int b = blockIdx.y, blk = blockIdx.x;
    const float* p = Y + (size_t)b * CDIM * HW + (size_t)blk * 32768;
    float s = 0.0f, q = 0.0f;
    for (int i = threadIdx.x; i < 32768; i += 256) {
        float v = p[i];
        s += v;
        q = fmaf(v, v, q);
    }
    __shared__ float ss[256], sq[256];
    ss[threadIdx.x] = s; sq[threadIdx.x] = q;
    __syncthreads();
    for (int st = 128; st > 0; st >>= 1) {
        if (threadIdx.x < st) {
            ss[threadIdx.x] += ss[threadIdx.x + st];
            sq[threadIdx.x] += sq[threadIdx.x + st];
        }
        __syncthreads();
    }
    if (threadIdx.x == 0) {
        g_psum[b * 64 + blk] = ss[0];
        g_psq [b * 64 + blk] = sq[0];
    }
}

__global__ void finalize_stats()
{
    const int b = blockIdx.x;
    const int t = threadIdx.x;
    __shared__ float ss[64], sq[64];
    ss[t] = g_psum[b * 64 + t];
    sq[t] = g_psq [b * 64 + t];
    __syncthreads();
    for (int st = 32; st > 0; st >>= 1) {
        if (t < st) { ss[t] += ss[t + st]; sq[t] += sq[t + st]; }
        __syncthreads();
    }
    if (t == 0) {
        const float inv_n = 1.0f / (float)(CDIM * HW);
        float mean = ss[0] * inv_n;
        float var  = sq[0] * inv_n - mean * mean;
        g_stats[b * 2 + 0] = mean;
        g_stats[b * 2 + 1] = rsqrtf(var + LN_EPS);
    }
}

__global__ void apply_ln(float* __restrict__ Y,
                         const float* __restrict__ gamma,
                         const float* __restrict__ beta)
{
    size_t i4 = (size_t)blockIdx.x * blockDim.x + threadIdx.x;
    int b = (int)(i4 >> 19);
    int c = (int)((i4 >> 10) & 511);
    float mean = g_stats[b * 2 + 0];
    float inv  = g_stats[b * 2 + 1];
    float g  = gamma[c] * inv;
    float bt = fmaf(-mean, g, beta[c]);
    float4 v = ((float4*)Y)[i4];
    v.x = fmaf(v.x, g, bt);
    v.y = fmaf(v.y, g, bt);
    v.z = fmaf(v.z, g, bt);
    v.w = fmaf(v.w, g, bt);
    ((float4*)Y)[i4] = v;
}

// ---------------------------------------------------------------------------
extern "C" void kernel_launch(void* const* d_in, const int* in_sizes, int n_in,
                              void* d_out, int out_size)
{
    const float* x      = (const float*)d_in[0];
    const float* w_qkv  = (const float*)d_in[1];
    const float* w_out  = (const float*)d_in[2];
    const float* b_out  = (const float*)d_in[3];
    const float* gamma  = (const float*)d_in[4];
    const float* beta   = (const float*)d_in[5];
    float* out = (float*)d_out;

    __nv_bfloat16 *xH, *xL, *wqH, *wqL, *woH, *woL, *wvtH, *wvtL;
    __nv_bfloat16 *GH, *GL, *UTH, *UTL, *AbdH, *AbdL, *MTH, *MTL, *PH, *PL;
    float *Sp;
    cudaGetSymbolAddress((void**)&xH,   g_xH);
    cudaGetSymbolAddress((void**)&xL,   g_xL);
    cudaGetSymbolAddress((void**)&wqH,  g_wqkvH);
    cudaGetSymbolAddress((void**)&wqL,  g_wqkvL);
    cudaGetSymbolAddress((void**)&woH,  g_woutH);
    cudaGetSymbolAddress((void**)&woL,  g_woutL);
    cudaGetSymbolAddress((void**)&wvtH, g_wvtH);
    cudaGetSymbolAddress((void**)&wvtL, g_wvtL);
    cudaGetSymbolAddress((void**)&GH,   g_GH);
    cudaGetSymbolAddress((void**)&GL,   g_GL);
    cudaGetSymbolAddress((void**)&UTH,  g_UTH);
    cudaGetSymbolAddress((void**)&UTL,  g_UTL);
    cudaGetSymbolAddress((void**)&Sp,   g_S);
    cudaGetSymbolAddress((void**)&AbdH, g_AbdH);
    cudaGetSymbolAddress((void**)&AbdL, g_AbdL);
    cudaGetSymbolAddress((void**)&MTH,  g_MTH);
    cudaGetSymbolAddress((void**)&MTL,  g_MTL);
    cudaGetSymbolAddress((void**)&PH,   g_PH);
    cudaGetSymbolAddress((void**)&PL,   g_PL);

    cudaFuncSetAttribute(gemm_nt128,
                         cudaFuncAttributeMaxDynamicSharedMemorySize, NT_SMEM);
    cudaFuncSetAttribute(gemm_bf16x3,
                         cudaFuncAttributeMaxDynamicSharedMemorySize, GEMM_SMEM_BYTES);

    const size_t S2 = (size_t)CDIM * CDIM;     // 512*512

    // 0) operand prep
    split_kernel<<<(MQKV * CDIM / 4 + 255) / 256, 256>>>(w_qkv, wqH, wqL, MQKV * CDIM / 4);
    split_kernel<<<(CDIM * CDIM / 4 + 255) / 256, 256>>>(w_out, woH, woL, CDIM * CDIM / 4);
    transpose_split_512<<<dim3(16, 16), dim3(32, 8)>>>(w_qkv + (size_t)1024 * CDIM, wvtH, wvtL);
    {
        int n4 = (int)((size_t)BATCH * CDIM * HW / 4);
        split_kernel<<<(n4 + 255) / 256, 256>>>(x, xH, xL, n4);
    }

    // 1) Gram: G_b = x_b x_b^T   (K = 4096)
    gemm_nt128<<<dim3(4, 4, BATCH), 256, NT_SMEM>>>(
        xH, xL, (size_t)CDIM * HW, xH, xL, (size_t)CDIM * HW, HW,
        nullptr, GH, GL, S2, CDIM);

    // 2) UT_b = W_k G_b   (W_k = rows 512..1023 of w_qkv)
    gemm_nt128<<<dim3(4, 4, BATCH), 256, NT_SMEM>>>(
        wqH + 512 * CDIM, wqL + 512 * CDIM, 0, GH, GL, S2, CDIM,
        nullptr, UTH, UTL, S2, CDIM);

    // 3) S_b = W_q UT_b^T = W_q G W_k^T   (fp32; diag head blocks used)
    gemm_nt128<<<dim3(4, 4, BATCH), 256, NT_SMEM>>>(
        wqH, wqL, 0, UTH, UTL, S2, CDIM,
        Sp, nullptr, nullptr, S2, CDIM);

    // 4) softmax on diagonal blocks -> block-diagonal attn (bf16 pair)
    softmax_blockdiag<<<dim3(NHEADS, BATCH), 64>>>();

    // 5) MT_b = W_v^T Abd_b^T   ( = (A W_v)^T )
    gemm_nt128<<<dim3(4, 4, BATCH), 256, NT_SMEM>>>(
        wvtH, wvtL, 0, AbdH, AbdL, S2, CDIM,
        nullptr, MTH, MTL, S2, CDIM);

    // 6) P_b = W_out (A W_v)   (K-major rows for the final GEMM)
    gemm_nt128<<<dim3(4, 4, BATCH), 256, NT_SMEM>>>(
        woH, woL, 0, MTH, MTL, S2, CDIM,
        nullptr, PH, PL, S2, CDIM);

    // 7) y_b = P_b x_b + b_out
    gemm_bf16x3<<<dim3(HW / 128, CDIM / 128, BATCH), 256, GEMM_SMEM_BYTES>>>(
        PH, PL, S2, xH, xL, out, b_out, CDIM, CDIM);

    // 8) per-batch LayerNorm
    reduce_partial<<<dim3(64, BATCH), 256>>>(out);
    finalize_stats<<<BATCH, 64>>>();
    apply_ln<<<(BATCH * CDIM * HW / 4) / 256, 256>>>(out, gamma, beta);
}

// round 17
// speedup vs baseline: 4.3614x; 1.0949x over previous
#include <cuda_runtime.h>
#include <cuda_bf16.h>
#include <math.h>
#include <stdint.h>

#define BATCH   16
#define CDIM    512
#define HW      4096
#define MQKV    1536
#define NHEADS  8
#define DHEAD   64
#define LN_EPS  1e-5f

// ---------------- scratch (device globals; no cudaMalloc allowed) ----------
__device__ __nv_bfloat16 g_xH  [(size_t)BATCH * CDIM * HW];   // x hi [b][c][n]
__device__ __nv_bfloat16 g_xL  [(size_t)BATCH * CDIM * HW];
__device__ __nv_bfloat16 g_wqkvH[1024 * CDIM];   // Wq,Wk rows
__device__ __nv_bfloat16 g_wqkvL[1024 * CDIM];
__device__ __nv_bfloat16 g_woutH[CDIM * CDIM];
__device__ __nv_bfloat16 g_woutL[CDIM * CDIM];
__device__ __nv_bfloat16 g_wvtH [CDIM * CDIM];   // W_v transposed
__device__ __nv_bfloat16 g_wvtL [CDIM * CDIM];
__device__ __nv_bfloat16 g_GH [(size_t)BATCH * CDIM * CDIM];  // Gram = x x^T
__device__ __nv_bfloat16 g_GL [(size_t)BATCH * CDIM * CDIM];
__device__ __nv_bfloat16 g_UTH[(size_t)BATCH * CDIM * CDIM];  // Y = Wq G
__device__ __nv_bfloat16 g_UTL[(size_t)BATCH * CDIM * CDIM];
__device__ float         g_S  [(size_t)BATCH * CDIM * CDIM];  // diag blocks used
__device__ __nv_bfloat16 g_AbdH[(size_t)BATCH * CDIM * CDIM]; // block-diag attn
__device__ __nv_bfloat16 g_AbdL[(size_t)BATCH * CDIM * CDIM];
__device__ __nv_bfloat16 g_MTH[(size_t)BATCH * CDIM * CDIM];  // (A Wv)^T
__device__ __nv_bfloat16 g_MTL[(size_t)BATCH * CDIM * CDIM];
__device__ __nv_bfloat16 g_PH [(size_t)BATCH * CDIM * CDIM];  // W_out A Wv
__device__ __nv_bfloat16 g_PL [(size_t)BATCH * CDIM * CDIM];
__device__ float         g_psum[BATCH * 128];
__device__ float         g_psq [BATCH * 128];
__device__ float         g_stats[BATCH * 2];

// ---------------- helpers ---------------------------------------------------
__device__ __forceinline__ void bf16_split(float x, unsigned short& h, unsigned short& l) {
    __nv_bfloat16 hb = __float2bfloat16_rn(x);
    float r = x - __bfloat162float(hb);
    __nv_bfloat16 lb = __float2bfloat16_rn(r);
    h = __bfloat16_as_ushort(hb);
    l = __bfloat16_as_ushort(lb);
}

__device__ __forceinline__ void mma_bf16(float* d, const uint32_t* a,
                                         const uint32_t* b, const float* c) {
    asm volatile(
        "mma.sync.aligned.m16n8k16.row.col.f32.bf16.bf16.f32 "
        "{%0,%1,%2,%3}, {%4,%5,%6,%7}, {%8,%9}, {%10,%11,%12,%13};\n"
        : "=f"(d[0]), "=f"(d[1]), "=f"(d[2]), "=f"(d[3])
        : "r"(a[0]), "r"(a[1]), "r"(a[2]), "r"(a[3]),
          "r"(b[0]), "r"(b[1]),
          "f"(c[0]), "f"(c[1]), "f"(c[2]), "f"(c[3]));
}
#define LDMX4(rg, addr) \
    asm volatile("ldmatrix.sync.aligned.m8n8.x4.shared.b16 {%0,%1,%2,%3}, [%4];" \
        : "=r"(rg[0]), "=r"(rg[1]), "=r"(rg[2]), "=r"(rg[3]) : "r"(addr))
#define LDMX4T(rg, addr) \
    asm volatile("ldmatrix.sync.aligned.m8n8.x4.trans.shared.b16 {%0,%1,%2,%3}, [%4];" \
        : "=r"(rg[0]), "=r"(rg[1]), "=r"(rg[2]), "=r"(rg[3]) : "r"(addr))
#define CP_ASYNC16(dst_u32, src_ptr) \
    asm volatile("cp.async.cg.shared.global [%0], [%1], 16;" \
        :: "r"(dst_u32), "l"(src_ptr))
#define CP_COMMIT() asm volatile("cp.async.commit_group;" ::: "memory")
#define CP_WAIT0()  asm volatile("cp.async.wait_group 0;" ::: "memory")

// ---------------- split fp32 -> (bf16 hi, bf16 lo) -------------------------
__global__ void split_kernel(const float* __restrict__ in,
                             __nv_bfloat16* __restrict__ hi,
                             __nv_bfloat16* __restrict__ lo, int n4)
{
    int i = blockIdx.x * blockDim.x + threadIdx.x;
    if (i >= n4) return;
    float4 v = ((const float4*)in)[i];
    unsigned short h[4], l[4];
    bf16_split(v.x, h[0], l[0]);
    bf16_split(v.y, h[1], l[1]);
    bf16_split(v.z, h[2], l[2]);
    bf16_split(v.w, h[3], l[3]);
    ((uint2*)hi)[i] = make_uint2((uint32_t)h[0] | ((uint32_t)h[1] << 16),
                                 (uint32_t)h[2] | ((uint32_t)h[3] << 16));
    ((uint2*)lo)[i] = make_uint2((uint32_t)l[0] | ((uint32_t)l[1] << 16),
                                 (uint32_t)l[2] | ((uint32_t)l[3] << 16));
}

// ---------------- transpose-split 512x512 (for Wv) -------------------------
__global__ void transpose_split_512(const float* __restrict__ w,
                                    __nv_bfloat16* __restrict__ th,
                                    __nv_bfloat16* __restrict__ tl)
{
    __shared__ float t[32][33];
    const int r0 = blockIdx.y * 32, c0 = blockIdx.x * 32;
    const int tx = threadIdx.x, ty = threadIdx.y;   // (32, 8)
#pragma unroll
    for (int i = 0; i < 4; i++)
        t[ty + i * 8][tx] = w[(size_t)(r0 + ty + i * 8) * CDIM + c0 + tx];
    __syncthreads();
#pragma unroll
    for (int i = 0; i < 4; i++) {
        float v = t[tx][ty + i * 8];
        unsigned short h, l;
        bf16_split(v, h, l);
        size_t dst = (size_t)(c0 + ty + i * 8) * CDIM + r0 + tx;
        th[dst] = __ushort_as_bfloat16(h);
        tl[dst] = __ushort_as_bfloat16(l);
    }
}

// ---------------------------------------------------------------------------
// nt GEMM (bf16x3): C[b][m][n] = sum_k A[b][m][k] * B[b][n][k]
// diag: m0 = n0 (grid (4,1,Z)). kWin: contraction window [n0, n0+kWin).
// ---------------------------------------------------------------------------
#define NT_ROW   40
#define NT_MAT_B (128 * NT_ROW * 2)       // 10240
#define NT_STG   (4 * NT_MAT_B)           // 40960
#define NT_SMEM  (2 * NT_STG)             // 81920

__global__ __launch_bounds__(256, 2)
void gemm_nt128(const __nv_bfloat16* __restrict__ AH, const __nv_bfloat16* __restrict__ AL,
                size_t aStr,
                const __nv_bfloat16* __restrict__ BH, const __nv_bfloat16* __restrict__ BL,
                size_t bStr, int K,
                float* __restrict__ outF,
                __nv_bfloat16* __restrict__ outH, __nv_bfloat16* __restrict__ outL,
                size_t oStr, int ldc, int diag, int kWin)
{
    extern __shared__ uint8_t sm[];
    const uint32_t sb = (uint32_t)__cvta_generic_to_shared(sm);

    const int b  = blockIdx.z;
    const int n0 = blockIdx.x * 128;
    const int m0 = diag ? n0 : blockIdx.y * 128;
    const int kOff = kWin ? n0 : 0;
    const int Keff = kWin ? kWin : K;
    const int tid = threadIdx.x;
    const int wid = tid >> 5, lane = tid & 31;
    const int wm = (wid >> 2) * 64;
    const int wn = (wid & 3) * 32;
    const int r = lane >> 2, c = lane & 3;

    const __nv_bfloat16* AHp = AH + b * aStr + (size_t)m0 * K + kOff;
    const __nv_bfloat16* ALp = AL + b * aStr + (size_t)m0 * K + kOff;
    const __nv_bfloat16* BHp = BH + b * bStr + (size_t)n0 * K + kOff;
    const __nv_bfloat16* BLp = BL + b * bStr + (size_t)n0 * K + kOff;

    float acc[4][4][4];
#pragma unroll
    for (int mt = 0; mt < 4; mt++)
#pragma unroll
        for (int nt = 0; nt < 4; nt++)
#pragma unroll
            for (int i = 0; i < 4; i++) acc[mt][nt][i] = 0.0f;

    auto load_stage = [&](int it) {
        const int k0 = it << 5;
        const uint32_t st = sb + (uint32_t)((it & 1) * NT_STG);
#pragma unroll
        for (int i = 0; i < 2; i++) {
            int seg = i * 256 + tid;            // 512 16B segs per matrix
            int row = seg >> 2, c16 = seg & 3;
            uint32_t d = st + (uint32_t)((row * NT_ROW + c16 * 8) * 2);
            size_t go = (size_t)row * K + k0 + c16 * 8;
            CP_ASYNC16(d,                AHp + go);
            CP_ASYNC16(d + NT_MAT_B,     ALp + go);
            CP_ASYNC16(d + 2 * NT_MAT_B, BHp + go);
            CP_ASYNC16(d + 3 * NT_MAT_B, BLp + go);
        }
        CP_COMMIT();
    };

    const uint32_t a_off = (uint32_t)(((wm + (lane & 15)) * NT_ROW + ((lane >> 4) & 1) * 8) * 2);

    load_stage(0);
    const int NITER = Keff >> 5;
    for (int it = 0; it < NITER; it++) {
        CP_WAIT0();
        __syncthreads();
        if (it + 1 < NITER) load_stage(it + 1);

        const uint32_t st = sb + (uint32_t)((it & 1) * NT_STG);
#pragma unroll
        for (int ks = 0; ks < 32; ks += 16) {
            uint32_t bH[4][2], bL[4][2];
#pragma unroll
            for (int p = 0; p < 2; p++) {
                uint32_t boff = (uint32_t)(((wn + p * 16 + (lane & 15)) * NT_ROW
                                            + ((lane >> 4) & 1) * 8 + ks) * 2);
                uint32_t rg[4];
                LDMX4(rg, st + 2 * NT_MAT_B + boff);
                bH[2*p][0] = rg[0]; bH[2*p][1] = rg[2];
                bH[2*p+1][0] = rg[1]; bH[2*p+1][1] = rg[3];
                LDMX4(rg, st + 3 * NT_MAT_B + boff);
                bL[2*p][0] = rg[0]; bL[2*p][1] = rg[2];
                bL[2*p+1][0] = rg[1]; bL[2*p+1][1] = rg[3];
            }
#pragma unroll
            for (int mt = 0; mt < 4; mt++) {
                uint32_t aH[4], aL[4];
                uint32_t ao = a_off + (uint32_t)((mt * 16 * NT_ROW + ks) * 2);
                LDMX4(aH, st + ao);
                LDMX4(aL, st + NT_MAT_B + ao);
#pragma unroll
                for (int nt = 0; nt < 4; nt++) {
                    mma_bf16(acc[mt][nt], aL, bH[nt], acc[mt][nt]);
                    mma_bf16(acc[mt][nt], aH, bL[nt], acc[mt][nt]);
                    mma_bf16(acc[mt][nt], aH, bH[nt], acc[mt][nt]);
                }
            }
        }
    }

    if (outF) {
        float* Cp = outF + b * oStr;
#pragma unroll
        for (int mt = 0; mt < 4; mt++) {
            const int row0 = m0 + wm + mt * 16 + r;
#pragma unroll
            for (int nt = 0; nt < 4; nt++) {
                const int col = n0 + wn + nt * 8 + 2 * c;
                *(float2*)(Cp + (size_t)row0       * ldc + col) =
                    make_float2(acc[mt][nt][0], acc[mt][nt][1]);
                *(float2*)(Cp + (size_t)(row0 + 8) * ldc + col) =
                    make_float2(acc[mt][nt][2], acc[mt][nt][3]);
            }
        }
    } else {
#pragma unroll
        for (int mt = 0; mt < 4; mt++) {
            const int row0 = m0 + wm + mt * 16 + r;
#pragma unroll
            for (int nt = 0; nt < 4; nt++) {
                const int col = n0 + wn + nt * 8 + 2 * c;
                unsigned short h0, l0, h1, l1;
                size_t o0 = b * oStr + (size_t)row0 * ldc + col;
                size_t o1 = b * oStr + (size_t)(row0 + 8) * ldc + col;
                bf16_split(acc[mt][nt][0], h0, l0);
                bf16_split(acc[mt][nt][1], h1, l1);
                *(uint32_t*)&outH[o0] = (uint32_t)h0 | ((uint32_t)h1 << 16);
                *(uint32_t*)&outL[o0] = (uint32_t)l0 | ((uint32_t)l1 << 16);
                bf16_split(acc[mt][nt][2], h0, l0);
                bf16_split(acc[mt][nt][3], h1, l1);
                *(uint32_t*)&outH[o1] = (uint32_t)h0 | ((uint32_t)h1 << 16);
                *(uint32_t*)&outL[o1] = (uint32_t)l0 | ((uint32_t)l1 << 16);
            }
        }
    }
}

// ---------------------------------------------------------------------------
// Final GEMM: Y[b][m][n] = sum_k A[b][m][k]*B[b][k][n] + bias[m], fp32 out.
// Also emits per-CTA (sum, sumsq) partials for the LayerNorm (deterministic).
// ---------------------------------------------------------------------------
#define A_ROW   40
#define B_ROW   136
#define A_TILE_B (128 * A_ROW * 2)
#define B_TILE_B (32 * B_ROW * 2)
#define OFF_AH  0
#define OFF_AL  (A_TILE_B)
#define OFF_BH  (2 * A_TILE_B)
#define OFF_BL  (2 * A_TILE_B + B_TILE_B)
#define STAGE_B (2 * A_TILE_B + 2 * B_TILE_B)
#define GEMM_SMEM_BYTES (2 * STAGE_B)

__global__ __launch_bounds__(256, 2)
void gemm_bf16x3(const __nv_bfloat16* __restrict__ AH, const __nv_bfloat16* __restrict__ AL,
                 size_t aStr,
                 const __nv_bfloat16* __restrict__ BH, const __nv_bfloat16* __restrict__ BL,
                 float* __restrict__ Yf, const float* __restrict__ bias, int K, int M)
{
    extern __shared__ uint8_t sm[];
    const uint32_t sbase = (uint32_t)__cvta_generic_to_shared(sm);

    const int b   = blockIdx.z;
    const int m0  = blockIdx.y * 128;
    const int n0  = blockIdx.x * 128;
    const int tid = threadIdx.x;
    const int wid = tid >> 5, lane = tid & 31;
    const int wm  = (wid >> 2) * 64;
    const int wn  = (wid & 3) * 32;
    const int r   = lane >> 2, c = lane & 3;

    const __nv_bfloat16* AHp = AH + b * aStr + (size_t)m0 * K;
    const __nv_bfloat16* ALp = AL + b * aStr + (size_t)m0 * K;
    const __nv_bfloat16* BHp = BH + (size_t)b * K * HW + n0;
    const __nv_bfloat16* BLp = BL + (size_t)b * K * HW + n0;

    float acc[4][4][4];
#pragma unroll
    for (int mt = 0; mt < 4; mt++)
#pragma unroll
        for (int nt = 0; nt < 4; nt++)
#pragma unroll
            for (int i = 0; i < 4; i++) acc[mt][nt][i] = 0.0f;

    const uint32_t a_lane_off = (uint32_t)(((wm + (lane & 15)) * A_ROW + ((lane >> 4) & 1) * 8) * 2);
    const uint32_t b_lane_off = (uint32_t)(((lane & 15) * B_ROW + wn + ((lane >> 4) & 1) * 8) * 2);

    const int NITER = K >> 5;

    auto load_stage = [&](int it) {
        const int k0 = it << 5;
        const uint32_t st = sbase + (uint32_t)((it & 1) * STAGE_B);
#pragma unroll
        for (int i = 0; i < 2; i++) {
            int seg = i * 256 + tid;
            int row = seg >> 2, c16 = seg & 3;
            uint32_t d = st + (uint32_t)((row * A_ROW + c16 * 8) * 2);
            size_t go = (size_t)row * K + k0 + c16 * 8;
            CP_ASYNC16(d + OFF_AH, AHp + go);
            CP_ASYNC16(d + OFF_AL, ALp + go);
        }
#pragma unroll
        for (int i = 0; i < 2; i++) {
            int seg = i * 256 + tid;
            int row = seg >> 4, c16 = seg & 15;
            uint32_t d = st + (uint32_t)((row * B_ROW + c16 * 8) * 2);
            size_t go = (size_t)(k0 + row) * HW + c16 * 8;
            CP_ASYNC16(d + OFF_BH, BHp + go);
            CP_ASYNC16(d + OFF_BL, BLp + go);
        }
        CP_COMMIT();
    };

    load_stage(0);

    for (int it = 0; it < NITER; it++) {
        CP_WAIT0();
        __syncthreads();
        if (it + 1 < NITER) load_stage(it + 1);

        const uint32_t st = sbase + (uint32_t)((it & 1) * STAGE_B);
        const uint32_t aH0 = st + OFF_AH + a_lane_off;
        const uint32_t aL0 = st + OFF_AL + a_lane_off;
        const uint32_t bH0 = st + OFF_BH + b_lane_off;
        const uint32_t bL0 = st + OFF_BL + b_lane_off;

#pragma unroll
        for (int ks = 0; ks < 32; ks += 16) {
            uint32_t bfH[4][2], bfL[4][2];
#pragma unroll
            for (int p = 0; p < 2; p++) {
                uint32_t rg[4];
                LDMX4T(rg, bH0 + (uint32_t)((ks * B_ROW + p * 16) * 2));
                bfH[2*p][0] = rg[0]; bfH[2*p][1] = rg[1];
                bfH[2*p+1][0] = rg[2]; bfH[2*p+1][1] = rg[3];
                LDMX4T(rg, bL0 + (uint32_t)((ks * B_ROW + p * 16) * 2));
                bfL[2*p][0] = rg[0]; bfL[2*p][1] = rg[1];
                bfL[2*p+1][0] = rg[2]; bfL[2*p+1][1] = rg[3];
            }
#pragma unroll
            for (int mt = 0; mt < 4; mt++) {
                uint32_t aHf[4], aLf[4];
                LDMX4(aHf, aH0 + (uint32_t)((mt * 16 * A_ROW + ks) * 2));
                LDMX4(aLf, aL0 + (uint32_t)((mt * 16 * A_ROW + ks) * 2));
#pragma unroll
                for (int nt = 0; nt < 4; nt++) {
                    mma_bf16(acc[mt][nt], aLf, bfH[nt], acc[mt][nt]);
                    mma_bf16(acc[mt][nt], aHf, bfL[nt], acc[mt][nt]);
                    mma_bf16(acc[mt][nt], aHf, bfH[nt], acc[mt][nt]);
                }
            }
        }
    }

    // epilogue: store + accumulate LN partials
    float s = 0.0f, q = 0.0f;
    float* Yp = Yf + (size_t)b * M * HW;
#pragma unroll
    for (int mt = 0; mt < 4; mt++) {
        const int row0 = m0 + wm + mt * 16 + r;
        const float b0v = bias ? bias[row0]     : 0.0f;
        const float b1v = bias ? bias[row0 + 8] : 0.0f;
#pragma unroll
        for (int nt = 0; nt < 4; nt++) {
            const int col = n0 + wn + nt * 8 + 2 * c;
            float v0 = acc[mt][nt][0] + b0v, v1 = acc[mt][nt][1] + b0v;
            float v2 = acc[mt][nt][2] + b1v, v3 = acc[mt][nt][3] + b1v;
            *(float2*)(Yp + (size_t)row0       * HW + col) = make_float2(v0, v1);
            *(float2*)(Yp + (size_t)(row0 + 8) * HW + col) = make_float2(v2, v3);
            s += v0 + v1 + v2 + v3;
            q = fmaf(v0, v0, q); q = fmaf(v1, v1, q);
            q = fmaf(v2, v2, q); q = fmaf(v3, v3, q);
        }
    }
    __syncthreads();                        // smem reuse for reduction
    float* red = (float*)sm;
    red[tid] = s; red[256 + tid] = q;
    __syncthreads();
    for (int st = 128; st > 0; st >>= 1) {
        if (tid < st) {
            red[tid]       += red[tid + st];
            red[256 + tid] += red[256 + tid + st];
        }
        __syncthreads();
    }
    if (tid == 0) {
        int slot = b * 128 + blockIdx.y * 32 + blockIdx.x;
        g_psum[slot] = red[0];
        g_psq [slot] = red[256];
    }
}

// ---------------------------------------------------------------------------
// Softmax over diagonal 64x64 blocks of S -> block-diag attn (bf16 pair).
// Zeroes only the sibling 64-block inside the 128-wide pair window.
// ---------------------------------------------------------------------------
__global__ void softmax_blockdiag()
{
    const int h = blockIdx.x, b = blockIdx.y;
    const int d = threadIdx.x;   // 0..63
    const float* srow = g_S + ((size_t)b * CDIM + h * DHEAD + d) * CDIM + h * DHEAD;

    float row[64];
    float m = -1e30f;
#pragma unroll
    for (int e = 0; e < 64; e++) { row[e] = srow[e] * 0.125f; m = fmaxf(m, row[e]); }
    float s = 0.0f;
#pragma unroll
    for (int e = 0; e < 64; e++) { row[e] = __expf(row[e] - m); s += row[e]; }
    const float inv = 1.0f / s;

    __nv_bfloat16* rh = g_AbdH + ((size_t)b * CDIM + h * DHEAD + d) * CDIM;
    __nv_bfloat16* rl = g_AbdL + ((size_t)b * CDIM + h * DHEAD + d) * CDIM;
    const int sib = (h ^ 1) * DHEAD;   // sibling head block within pair window
#pragma unroll
    for (int j = 0; j < 16; j++) {
        ((uint2*)(rh + sib))[j] = make_uint2(0u, 0u);
        ((uint2*)(rl + sib))[j] = make_uint2(0u, 0u);
    }
#pragma unroll
    for (int e4 = 0; e4 < 16; e4++) {
        unsigned short hh[4], ll[4];
#pragma unroll
        for (int q = 0; q < 4; q++) bf16_split(row[e4 * 4 + q] * inv, hh[q], ll[q]);
        ((uint2*)(rh + h * DHEAD))[e4] = make_uint2((uint32_t)hh[0] | ((uint32_t)hh[1] << 16),
                                                    (uint32_t)hh[2] | ((uint32_t)hh[3] << 16));
        ((uint2*)(rl + h * DHEAD))[e4] = make_uint2((uint32_t)ll[0] | ((uint32_t)ll[1] << 16),
                                                    (uint32_t)ll[2] | ((uint32_t)ll[3] << 16));
    }
}

// ---------------------------------------------------------------------------
// LayerNorm finalize + apply
// ---------------------------------------------------------------------------
__global__ void finalize_stats()
{
    const int b = blockIdx.x;
    const int t = threadIdx.x;   // 128 threads
    __shared__ float ss[128], sq[128];
    ss[t] = g_psum[b * 128 + t];
    sq[t] = g_psq [b * 128 + t];
    __syncthreads();
    for (int st = 64; st > 0; st >>= 1) {
        if (t < st) { ss[t] += ss[t + st]; sq[t] += sq[t + st]; }
        __syncthreads();
    }
    if (t == 0) {
        const float inv_n = 1.0f / (float)(CDIM * HW);
        float mean = ss[0] * inv_n;
        float var  = sq[0] * inv_n - mean * mean;
        g_stats[b * 2 + 0] = mean;
        g_stats[b * 2 + 1] = rsqrtf(var + LN_EPS);
    }
}

__global__ void apply_ln(float* __restrict__ Y,
                         const float* __restrict__ gamma,
                         const float* __restrict__ beta)
{
    size_t i4 = (size_t)blockIdx.x * blockDim.x + threadIdx.x;
    int b = (int)(i4 >> 19);
    int c = (int)((i4 >> 10) & 511);
    float mean = g_stats[b * 2 + 0];
    float inv  = g_stats[b * 2 + 1];
    float g  = gamma[c] * inv;
    float bt = fmaf(-mean, g, beta[c]);
    float4 v = ((float4*)Y)[i4];
    v.x = fmaf(v.x, g, bt);
    v.y = fmaf(v.y, g, bt);
    v.z = fmaf(v.z, g, bt);
    v.w = fmaf(v.w, g, bt);
    ((float4*)Y)[i4] = v;
}

// ---------------------------------------------------------------------------
extern "C" void kernel_launch(void* const* d_in, const int* in_sizes, int n_in,
                              void* d_out, int out_size)
{
    const float* x      = (const float*)d_in[0];
    const float* w_qkv  = (const float*)d_in[1];
    const float* w_out  = (const float*)d_in[2];
    const float* b_out  = (const float*)d_in[3];
    const float* gamma  = (const float*)d_in[4];
    const float* beta   = (const float*)d_in[5];
    float* out = (float*)d_out;

    __nv_bfloat16 *xH, *xL, *wqH, *wqL, *woH, *woL, *wvtH, *wvtL;
    __nv_bfloat16 *GH, *GL, *UTH, *UTL, *AbdH, *AbdL, *MTH, *MTL, *PH, *PL;
    float *Sp;
    cudaGetSymbolAddress((void**)&xH,   g_xH);
    cudaGetSymbolAddress((void**)&xL,   g_xL);
    cudaGetSymbolAddress((void**)&wqH,  g_wqkvH);
    cudaGetSymbolAddress((void**)&wqL,  g_wqkvL);
    cudaGetSymbolAddress((void**)&woH,  g_woutH);
    cudaGetSymbolAddress((void**)&woL,  g_woutL);
    cudaGetSymbolAddress((void**)&wvtH, g_wvtH);
    cudaGetSymbolAddress((void**)&wvtL, g_wvtL);
    cudaGetSymbolAddress((void**)&GH,   g_GH);
    cudaGetSymbolAddress((void**)&GL,   g_GL);
    cudaGetSymbolAddress((void**)&UTH,  g_UTH);
    cudaGetSymbolAddress((void**)&UTL,  g_UTL);
    cudaGetSymbolAddress((void**)&Sp,   g_S);
    cudaGetSymbolAddress((void**)&AbdH, g_AbdH);
    cudaGetSymbolAddress((void**)&AbdL, g_AbdL);
    cudaGetSymbolAddress((void**)&MTH,  g_MTH);
    cudaGetSymbolAddress((void**)&MTL,  g_MTL);
    cudaGetSymbolAddress((void**)&PH,   g_PH);
    cudaGetSymbolAddress((void**)&PL,   g_PL);

    cudaFuncSetAttribute(gemm_nt128,
                         cudaFuncAttributeMaxDynamicSharedMemorySize, NT_SMEM);
    cudaFuncSetAttribute(gemm_bf16x3,
                         cudaFuncAttributeMaxDynamicSharedMemorySize, GEMM_SMEM_BYTES);

    const size_t S2 = (size_t)CDIM * CDIM;

    // 0) operand prep (Wq,Wk K-major split; Wv transpose-split; x split)
    split_kernel<<<(1024 * CDIM / 4 + 255) / 256, 256>>>(w_qkv, wqH, wqL, 1024 * CDIM / 4);
    split_kernel<<<(CDIM * CDIM / 4 + 255) / 256, 256>>>(w_out, woH, woL, CDIM * CDIM / 4);
    transpose_split_512<<<dim3(16, 16), dim3(32, 8)>>>(w_qkv + (size_t)1024 * CDIM, wvtH, wvtL);
    {
        int n4 = (int)((size_t)BATCH * CDIM * HW / 4);
        split_kernel<<<(n4 + 255) / 256, 256>>>(x, xH, xL, n4);
    }

    // 1) Gram: G_b = x_b x_b^T  (K = 4096)
    gemm_nt128<<<dim3(4, 4, BATCH), 256, NT_SMEM>>>(
        xH, xL, (size_t)CDIM * HW, xH, xL, (size_t)CDIM * HW, HW,
        nullptr, GH, GL, S2, CDIM, 0, 0);

    // 2) Y_b = W_q G_b  (full)
    gemm_nt128<<<dim3(4, 4, BATCH), 256, NT_SMEM>>>(
        wqH, wqL, 0, GH, GL, S2, CDIM,
        nullptr, UTH, UTL, S2, CDIM, 0, 0);

    // 3) S diag blocks: S_t = Y_t W_k,t^T  (diagonal 128-tiles only)
    gemm_nt128<<<dim3(4, 1, BATCH), 256, NT_SMEM>>>(
        UTH, UTL, S2, wqH + 512 * CDIM, wqL + 512 * CDIM, 0, CDIM,
        Sp, nullptr, nullptr, S2, CDIM, 1, 0);

    // 4) softmax on diagonal head blocks -> block-diagonal attn
    softmax_blockdiag<<<dim3(NHEADS, BATCH), 64>>>();

    // 5) MT_b = W_v^T Abd_b^T  (contraction restricted to 128-wide pair window)
    gemm_nt128<<<dim3(4, 4, BATCH), 256, NT_SMEM>>>(
        wvtH, wvtL, 0, AbdH, AbdL, S2, CDIM,
        nullptr, MTH, MTL, S2, CDIM, 0, 128);

    // 6) P_b = W_out (A W_v)  (full)
    gemm_nt128<<<dim3(4, 4, BATCH), 256, NT_SMEM>>>(
        woH, woL, 0, MTH, MTL, S2, CDIM,
        nullptr, PH, PL, S2, CDIM, 0, 0);

    // 7) y_b = P_b x_b + b_out  (+ fused LN partial sums)
    gemm_bf16x3<<<dim3(HW / 128, CDIM / 128, BATCH), 256, GEMM_SMEM_BYTES>>>(
        PH, PL, S2, xH, xL, out, b_out, CDIM, CDIM);

    // 8) per-batch LayerNorm finalize + apply
    finalize_stats<<<BATCH, 128>>>();
    apply_ln<<<(BATCH * CDIM * HW / 4) / 256, 256>>>(out, gamma, beta);
}